// round 12
// baseline (speedup 1.0000x reference)
#include <cuda_runtime.h>
#include <cuda_bf16.h>
#include <math.h>

#define N0 4096
#define CH 256
#define DEG 96

#define MODE_DINV0 0
#define MODE_DINV  1
#define MODE_RELU  2

#define PAIRS_X   0x011000   // (a0,b0),(a1,b0),(a0,b1)
#define PAIRS_AGG 0x0100     // (a0,b0),(a0,b1)
#define PAIRS_AA  0x0

// ---------------- scratch (static device globals; no allocation) ----------------
static __device__ __align__(16) float g_part[2 * 4096 * 256];        // 8MB split-K partials
static __device__ __align__(16) float g_part2[2 * 1024 * 1024];      // 8MB AA partials
static __device__ __align__(16) __nv_bfloat16 g_Atb[2048 * 2048];
static __device__ __align__(16) __nv_bfloat16 g_Rb[1024 * 2048];
static __device__ __align__(16) __nv_bfloat16 g_Cbb[2048 * 1024];
static __device__ __align__(16) __nv_bfloat16 g_Xb[2 * N0 * CH];
static __device__ __align__(16) __nv_bfloat16 g_Wb[3 * 2 * CH * CH];
static __device__ __align__(16) __nv_bfloat16 g_xwb[2 * 2048 * CH];
static __device__ __align__(16) float g_fA[N0 * CH];
static __device__ __align__(16) float g_fB[N0 * CH];
static __device__ __align__(16) float g_fpart[32 * 256];
static __device__ float g_dinv[N0];
static __device__ float g_score[N0];
static __device__ int   g_perm[N0];
static __device__ int   g_csccnt[N0];
static __device__ int   g_srcs[N0 * DEG];
static __device__ int   g_cntdiag[N0];
static __device__ int   g_indeg[N0];

__device__ __forceinline__ unsigned fkey(float f) {
    unsigned u = __float_as_uint(f);
    return (u & 0x80000000u) ? ~u : (u | 0x80000000u);
}

// ---------------- zero + split-2 of x, w0, w1, w2 (merged) ----------------
__global__ void k_zs(const float* __restrict__ x, const float* __restrict__ w0,
                     const float* __restrict__ w1, const float* __restrict__ w2,
                     __nv_bfloat16* __restrict__ Xb, __nv_bfloat16* __restrict__ Wb) {
    const int nx = N0 * CH;
    const int nw = CH * CH;
    int id = blockIdx.x;
    if (id < 16) {
        int i = id * 256 + threadIdx.x;
        g_csccnt[i] = 0; g_cntdiag[i] = 0; g_indeg[i] = 0;
        return;
    }
    int idx = (id - 16) * 256 + threadIdx.x;
    float v; __nv_bfloat16 *hi, *lo;
    if (idx < nx) {
        v = x[idx];
        hi = Xb + idx; lo = Xb + nx + idx;
    } else {
        int j = idx - nx;
        if (j >= 3 * nw) return;
        int l = j >> 16, o = j & (nw - 1);
        v = (l == 0) ? w0[o] : (l == 1) ? w1[o] : w2[o];
        __nv_bfloat16* base = Wb + (size_t)l * 2 * nw;
        hi = base + o; lo = base + nw + o;
    }
    __nv_bfloat16 h = __float2bfloat16_rn(v);
    *hi = h;
    *lo = __float2bfloat16_rn(v - __bfloat162float(h));
}

// ---------------- bf16 HMMA GEMM body (R8-proven), as device function ----------------
__device__ __forceinline__ void mma16816(float* d, const unsigned* a, unsigned b0, unsigned b1) {
    asm volatile(
        "mma.sync.aligned.m16n8k16.row.col.f32.bf16.bf16.f32 "
        "{%0,%1,%2,%3}, {%4,%5,%6,%7}, {%8,%9}, {%0,%1,%2,%3};\n"
        : "+f"(d[0]), "+f"(d[1]), "+f"(d[2]), "+f"(d[3])
        : "r"(a[0]), "r"(a[1]), "r"(a[2]), "r"(a[3]), "r"(b0), "r"(b1));
}

template <int NA, int NB>
__host__ __device__ constexpr int hgemm_smem() {
    return 2 * (NA * 128 * 40 * 2 + NB * 16 * 136 * 4);
}

template <int NA, int NB, int NPAIR, int PAIRS>
__device__ void hgemm_body(const __nv_bfloat16* __restrict__ A, const __nv_bfloat16* __restrict__ B,
                           float* __restrict__ Cpart, int lda, int ldb, int chunk,
                           int M, int N, long aStride, long bStride,
                           int bidx, int bidy, int bidz, char* sm_raw) {
    __nv_bfloat16* Asm = (__nv_bfloat16*)sm_raw;                            // [2][NA][128][40]
    unsigned* Bsm = (unsigned*)(sm_raw + 2 * NA * 128 * 40 * 2);            // [2][NB][16][136]

    int tid = threadIdx.x;
    int i0 = bidy * 128, j0 = bidx * 128;
    int kbeg = bidz * chunk, kend = kbeg + chunk;
    int w = tid >> 5, l = tid & 31;
    int wm = w & 3, wn = w >> 2;
    int mb = wm * 32, nb = wn * 64;
    int g = l >> 2, tg = l & 3;

    float acc[2][8][4];
#pragma unroll
    for (int mt = 0; mt < 2; mt++)
#pragma unroll
        for (int j = 0; j < 8; j++)
#pragma unroll
            for (int q = 0; q < 4; q++) acc[mt][j][q] = 0.f;

    int arow = tid >> 1, apart = tid & 1;
    int bkk = tid >> 4, bnseg = tid & 15;

    auto stage = [&](int st, int k0) {
#pragma unroll
        for (int q = 0; q < NA; q++) {
            const uint4* src = (const uint4*)&A[q * aStride + (size_t)(i0 + arow) * lda + k0 + apart * 16];
            uint4* dst = (uint4*)(Asm + ((size_t)(st * NA + q) * 128 + arow) * 40 + apart * 16);
            dst[0] = src[0]; dst[1] = src[1];
        }
#pragma unroll
        for (int p = 0; p < NB; p++) {
            const __nv_bfloat16* Bp = B + p * bStride;
            uint4 lo4 = *(const uint4*)&Bp[(size_t)(k0 + 2 * bkk) * ldb + j0 + bnseg * 8];
            uint4 hi4 = *(const uint4*)&Bp[(size_t)(k0 + 2 * bkk + 1) * ldb + j0 + bnseg * 8];
            unsigned* d = Bsm + ((size_t)(st * NB + p) * 16 + bkk) * 136 + bnseg * 8;
            *(uint4*)d = make_uint4(
                __byte_perm(lo4.x, hi4.x, 0x5410), __byte_perm(lo4.x, hi4.x, 0x7632),
                __byte_perm(lo4.y, hi4.y, 0x5410), __byte_perm(lo4.y, hi4.y, 0x7632));
            *(uint4*)(d + 4) = make_uint4(
                __byte_perm(lo4.z, hi4.z, 0x5410), __byte_perm(lo4.z, hi4.z, 0x7632),
                __byte_perm(lo4.w, hi4.w, 0x5410), __byte_perm(lo4.w, hi4.w, 0x7632));
        }
    };

    stage(0, kbeg);
    __syncthreads();

    for (int k0 = kbeg; k0 < kend; k0 += 32) {
        int cur = ((k0 - kbeg) >> 5) & 1;
        if (k0 + 32 < kend) stage(cur ^ 1, k0 + 32);
#pragma unroll
        for (int ks = 0; ks < 32; ks += 16) {
            unsigned a[NA][2][4];
#pragma unroll
            for (int q = 0; q < NA; q++) {
                const __nv_bfloat16* Aq = Asm + (size_t)(cur * NA + q) * 128 * 40;
#pragma unroll
                for (int mt = 0; mt < 2; mt++) {
                    int r0 = mb + mt * 16 + g;
                    a[q][mt][0] = *(const unsigned*)(Aq + r0 * 40 + ks + tg * 2);
                    a[q][mt][1] = *(const unsigned*)(Aq + (r0 + 8) * 40 + ks + tg * 2);
                    a[q][mt][2] = *(const unsigned*)(Aq + r0 * 40 + ks + tg * 2 + 8);
                    a[q][mt][3] = *(const unsigned*)(Aq + (r0 + 8) * 40 + ks + tg * 2 + 8);
                }
            }
            int kk0 = (ks >> 1) + tg;
#pragma unroll
            for (int p = 0; p < NPAIR; p++) {
                const int ai = (PAIRS >> (8 * p + 4)) & 0xF;
                const int bi = (PAIRS >> (8 * p)) & 0xF;
                const unsigned* Bq = Bsm + (size_t)(cur * NB + bi) * 16 * 136;
#pragma unroll
                for (int j = 0; j < 8; j++) {
                    int n = nb + j * 8 + g;
                    unsigned b0 = Bq[kk0 * 136 + n];
                    unsigned b1 = Bq[(kk0 + 4) * 136 + n];
                    mma16816(acc[0][j], a[ai][0], b0, b1);
                    mma16816(acc[1][j], a[ai][1], b0, b1);
                }
            }
        }
        __syncthreads();
    }
    float* Cp = Cpart + (size_t)bidz * M * N;
#pragma unroll
    for (int mt = 0; mt < 2; mt++) {
        int gr = i0 + mb + mt * 16 + g;
#pragma unroll
        for (int j = 0; j < 8; j++) {
            int gc = j0 + nb + j * 8 + tg * 2;
            *(float2*)&Cp[(size_t)gr * N + gc] = make_float2(acc[mt][j][0], acc[mt][j][1]);
            *(float2*)&Cp[(size_t)(gr + 8) * N + gc] = make_float2(acc[mt][j][2], acc[mt][j][3]);
        }
    }
}

// standalone wrapper
template <int NA, int NB, int NPAIR, int PAIRS>
__global__ void __launch_bounds__(256, 1)
k_hgemm(const __nv_bfloat16* __restrict__ A, const __nv_bfloat16* __restrict__ B,
        float* __restrict__ Cpart, int lda, int ldb, int chunk,
        int M, int N, long aStride, long bStride) {
    extern __shared__ char sm_raw[];
    hgemm_body<NA, NB, NPAIR, PAIRS>(A, B, Cpart, lda, ldb, chunk, M, N, aStride, bStride,
                                     blockIdx.x, blockIdx.y, blockIdx.z, sm_raw);
}

// ---------------- augment body (dynamic smem) ----------------
__device__ void augmentT_body(__nv_bfloat16* __restrict__ Atb, int r, char* sm) {
    float* s = (float*)sm;                 // 16KB
    int* sp = (int*)(sm + 16384);          // 8KB
    float* red = (float*)(sm + 16384 + 8192);  // 1KB
    int t = threadIdx.x;
    for (int c = t; c < N0; c += 256) s[c] = 0.f;
    for (int c = t; c < 2048; c += 256) sp[c] = g_perm[c];
    __syncthreads();
    int i = sp[r];
    int lane = t & 31, w = t >> 5;
    int cnt = g_csccnt[i];
    const int* isrc = &g_srcs[i * DEG];
    for (int e = w; e < cnt; e += 8) {
        int kc = isrc[e];
        if (lane == 0) atomicAdd(&s[kc], 2.0f);
        int cnt2 = g_csccnt[kc];
        const int* ksrc = &g_srcs[kc * DEG];
        for (int f = lane; f < cnt2; f += 32) atomicAdd(&s[ksrc[f]], 1.0f);
    }
    __syncthreads();
    __nv_bfloat16* row = Atb + (size_t)r * 2048;
    float part = 0.f;
    for (int c = t; c < 2048; c += 256) {
        float v = (c == r) ? 2.0f : s[sp[c]];
        row[c] = __float2bfloat16_rn(v);
        part += v;
    }
    red[t] = part; __syncthreads();
    for (int off = 128; off > 0; off >>= 1) { if (t < off) red[t] += red[t + off]; __syncthreads(); }
    if (t == 0) g_dinv[r] = rsqrtf(red[0]);
}

// ---------------- merged launches ----------------
// L0: blocks [0,128) xw GEMM (grid 2,32,2); blocks [128,128+fillBlocks) edge fill
__global__ void __launch_bounds__(256, 1)
k_l0_par(const __nv_bfloat16* __restrict__ Xb, const __nv_bfloat16* __restrict__ Wb,
         float* __restrict__ Cpart, const int* __restrict__ ei, int E) {
    extern __shared__ char sm_raw[];
    int id = blockIdx.x;
    if (id < 128) {
        hgemm_body<2, 2, 3, PAIRS_X>(Xb, Wb, Cpart, 256, 256, 128, N0, 256,
                                     (long)N0 * CH, (long)CH * CH,
                                     id & 1, (id >> 1) & 31, id >> 6, sm_raw);
    } else {
        int e = (id - 128) * 256 + threadIdx.x;
        if (e >= E) return;
        int s = ei[e], d = ei[e + E];
        atomicAdd(&g_indeg[d], 1);
        if (s == d) {
            atomicAdd(&g_cntdiag[s], 1);
        } else {
            int pos = atomicAdd(&g_csccnt[d], 1);
            if (pos < DEG) g_srcs[d * DEG + pos] = s;
        }
    }
}

// L1: blocks [0,128) xw GEMM (grid 2,16,4); blocks [128,128+2048) augment rows
__global__ void __launch_bounds__(256, 1)
k_l1_par(const __nv_bfloat16* __restrict__ Xb, const __nv_bfloat16* __restrict__ Wb,
         float* __restrict__ Cpart, __nv_bfloat16* __restrict__ Atb) {
    extern __shared__ char sm_raw[];
    int id = blockIdx.x;
    if (id < 128) {
        hgemm_body<2, 2, 3, PAIRS_X>(Xb, Wb, Cpart, 256, 256, 64, 2048, 256,
                                     (long)2048 * CH, (long)CH * CH,
                                     id & 1, (id >> 1) & 15, id >> 5, sm_raw);
    } else {
        augmentT_body(Atb, id - 128, sm_raw);
    }
}

// L2a: gather_xb(k2) + gather_RC fused elementwise
__global__ void k_l2a_par(const float* __restrict__ src, __nv_bfloat16* __restrict__ dstX,
                          const __nv_bfloat16* __restrict__ At,
                          __nv_bfloat16* __restrict__ R, __nv_bfloat16* __restrict__ Cb,
                          int kold, int kn) {
    int idx = blockIdx.x * blockDim.x + threadIdx.x;
    int totx = kn * CH;
    int tot = kn * kold;
    if (idx < totx) {
        int r = idx >> 8;
        int p = g_perm[r];
        float v = src[(size_t)p * CH + (idx & 255)] * g_score[p];
        __nv_bfloat16 h = __float2bfloat16_rn(v);
        dstX[idx] = h;
        dstX[(size_t)kn * CH + idx] = __float2bfloat16_rn(v - __bfloat162float(h));
        return;
    }
    int j0 = idx - totx;
    if (j0 < tot) {
        int r = j0 / kold, k = j0 - r * kold;
        int p = g_perm[r];
        R[j0] = (k == p) ? __float2bfloat16_rn(1.0f) : At[(size_t)p * kold + k];
    } else if (j0 < 2 * tot) {
        int j = j0 - tot;
        int k = j / kn, c = j - k * kn;
        int p = g_perm[c];
        Cb[j] = (k == p) ? __float2bfloat16_rn(1.0f) : At[(size_t)k * kold + p];
    }
}

// L2b: blocks [0,128) xw GEMM (grid 2,8,8) -> Cp1; blocks [128,256) AA GEMM (grid 8,8,2) -> Cp2
__global__ void __launch_bounds__(256, 1)
k_l2b_par(const __nv_bfloat16* __restrict__ Xb, const __nv_bfloat16* __restrict__ Wb,
          float* __restrict__ Cp1,
          const __nv_bfloat16* __restrict__ Rb, const __nv_bfloat16* __restrict__ Cbb,
          float* __restrict__ Cp2) {
    extern __shared__ char sm_raw[];
    int id = blockIdx.x;
    if (id < 128) {
        hgemm_body<2, 2, 3, PAIRS_X>(Xb, Wb, Cp1, 256, 256, 32, 1024, 256,
                                     (long)1024 * CH, (long)CH * CH,
                                     id & 1, (id >> 1) & 7, id >> 4, sm_raw);
    } else {
        int aid = id - 128;
        hgemm_body<1, 1, 1, PAIRS_AA>(Rb, Cbb, Cp2, 2048, 1024, 1024, 1024, 1024,
                                      0, 0, aid & 7, (aid >> 3) & 7, aid >> 6, sm_raw);
    }
}

// ---------------- split-K reduce, one block per output row (N=256) ----------------
__global__ void k_reduceF(const float* __restrict__ Cpart, float* __restrict__ out,
                          int SK, int M, int mode, const float* __restrict__ bias,
                          const float* __restrict__ p) {
    __shared__ float red[256], red2[256];
    int row = blockIdx.x, t = threadIdx.x;
    int idx = row * 256 + t;
    float s = 0.f;
    for (int z = 0; z < SK; z++) s += Cpart[(size_t)z * M * 256 + idx];
    float v;
    if (mode == MODE_DINV0) {
        float deg = (float)g_indeg[row] + ((g_cntdiag[row] == 0) ? 2.0f : 0.0f);
        v = s * rsqrtf(deg);
    } else if (mode == MODE_DINV) {
        v = s * g_dinv[row];
    } else {
        v = fmaxf(g_dinv[row] * s + bias[t], 0.f);
    }
    out[idx] = v;
    if (p != nullptr) {
        float pv = p[t];
        red[t] = v * pv; red2[t] = pv * pv;
        __syncthreads();
        for (int off = 128; off > 0; off >>= 1) {
            if (t < off) { red[t] += red[t + off]; red2[t] += red2[t + off]; }
            __syncthreads();
        }
        if (t == 0) g_score[row] = tanhf(red[0] * rsqrtf(red2[0]));
    }
}

// split-K reduce -> dinv scale -> split-2 bf16 planes
__global__ void k_reduce_ds2(const float* __restrict__ Cpart, __nv_bfloat16* __restrict__ out,
                             int SK, int M, int N) {
    int idx = blockIdx.x * blockDim.x + threadIdx.x;
    if (idx >= M * N) return;
    float s = 0.f;
    for (int z = 0; z < SK; z++) s += Cpart[(size_t)z * M * N + idx];
    float v = s * g_dinv[idx / N];
    __nv_bfloat16 h = __float2bfloat16_rn(v);
    out[idx] = h;
    out[(size_t)M * N + idx] = __float2bfloat16_rn(v - __bfloat162float(h));
}

// split-K reduce for A2^T, one block per row
__global__ void k_reduce_A2t(const float* __restrict__ Cpart, __nv_bfloat16* __restrict__ out,
                             int n) {
    __shared__ float red[256];
    int row = blockIdx.x, t = threadIdx.x;
    float part = 0.f;
    for (int c = t; c < n; c += 256) {
        size_t idx = (size_t)row * n + c;
        float s = Cpart[idx] + Cpart[(size_t)n * n + idx];
        float v = (row == c) ? 2.0f : s;
        out[idx] = __float2bfloat16_rn(v);
        part += v;
    }
    red[t] = part; __syncthreads();
    for (int off = 128; off > 0; off >>= 1) { if (t < off) red[t] += red[t + off]; __syncthreads(); }
    if (t == 0) g_dinv[row] = rsqrtf(red[0]);
}

// ---------------- level-0 aggregation + fused score ----------------
__global__ void k_agg0(const float* __restrict__ B, const float* __restrict__ bias,
                       float* __restrict__ out, const float* __restrict__ p) {
    __shared__ float red[256], red2[256];
    int d = blockIdx.x, t = threadIdx.x;
    int cd = g_cntdiag[d];
    float w0 = (cd == 0) ? 2.0f : (float)cd;
    float acc = w0 * B[(size_t)d * CH + t];
    int cnt = g_csccnt[d];
    const int* src = &g_srcs[d * DEG];
#pragma unroll 4
    for (int e = 0; e < cnt; e++) {
        int s = __ldg(&src[e]);
        acc += B[(size_t)s * CH + t];
    }
    float deg = (float)g_indeg[d] + ((cd == 0) ? 2.0f : 0.0f);
    float v = fmaxf(rsqrtf(deg) * acc + bias[t], 0.0f);
    out[(size_t)d * CH + t] = v;
    float pv = p[t];
    red[t] = v * pv; red2[t] = pv * pv;
    __syncthreads();
    for (int off = 128; off > 0; off >>= 1) {
        if (t < off) { red[t] += red[t + off]; red2[t] += red2[t + off]; }
        __syncthreads();
    }
    if (t == 0) g_score[d] = tanhf(red[0] * rsqrtf(red2[0]));
}

// ---------------- top-k threshold + collect ----------------
__global__ void k_threshcollect(int n, int k) {
    __shared__ unsigned u[N0];
    __shared__ int sc[2];
    int t = threadIdx.x;
    int per = n >> 10;
    for (int i = t; i < n; i += 1024) u[i] = fkey(g_score[i]);
    __syncthreads();
    unsigned thr = 0;
    for (int bit = 31; bit >= 0; --bit) {
        unsigned cand = thr | (1u << bit);
        int c = 0;
        for (int j = 0; j < per; j++)
            c += __syncthreads_count(u[j * 1024 + t] >= cand);
        if (c >= k) thr = cand;
    }
    int cg = 0;
    for (int j = 0; j < per; j++)
        cg += __syncthreads_count(u[j * 1024 + t] > thr);
    if (t == 0) { sc[0] = 0; sc[1] = 0; }
    __syncthreads();
    for (int i = t; i < n; i += 1024) {
        unsigned v = u[i];
        if (v > thr) {
            int p = atomicAdd(&sc[0], 1);
            g_perm[p] = i;
        } else if (v == thr) {
            int p = atomicAdd(&sc[1], 1);
            int pos = cg + p;
            if (pos < k) g_perm[pos] = i;
        }
    }
}

// gather + gate + split-2 bf16 (level 1)
__global__ void k_gather_xb(const float* __restrict__ src, __nv_bfloat16* __restrict__ dst, int k) {
    int idx = blockIdx.x * blockDim.x + threadIdx.x;
    if (idx >= k * CH) return;
    int r = idx >> 8;
    int p = g_perm[r];
    float v = src[(size_t)p * CH + (idx & 255)] * g_score[p];
    __nv_bfloat16 h = __float2bfloat16_rn(v);
    dst[idx] = h;
    dst[(size_t)k * CH + idx] = __float2bfloat16_rn(v - __bfloat162float(h));
}

// ---------------- final readout ----------------
__global__ void k_rowsum_f(const float* __restrict__ F, int n) {
    int t = threadIdx.x;
    int rows = n / 32;
    float s = 0.f;
    int r0 = blockIdx.x * rows;
    for (int r = r0; r < r0 + rows; r++) s += F[(size_t)r * CH + t];
    g_fpart[blockIdx.x * 256 + t] = s;
}

__global__ void k_final(int n, const float* __restrict__ wc,
                        const float* __restrict__ bc, float* __restrict__ out, int out_size) {
    __shared__ float red[256];
    __shared__ float lg[16];
    int t = threadIdx.x;
    float s = 0.f;
#pragma unroll
    for (int b = 0; b < 32; b++) s += g_fpart[b * 256 + t];
    float mv = s / (float)n;
    red[t] = mv * mv; __syncthreads();
    for (int off = 128; off > 0; off >>= 1) { if (t < off) red[t] += red[t + off]; __syncthreads(); }
    float nrm = fmaxf(sqrtf(red[0]), 1e-12f);
    __syncthreads();
    float e = mv / nrm;
    for (int j = 0; j < 10; j++) {
        red[t] = e * wc[j * CH + t]; __syncthreads();
        for (int off = 128; off > 0; off >>= 1) { if (t < off) red[t] += red[t + off]; __syncthreads(); }
        if (t == 0) lg[j] = red[0] + bc[j];
        __syncthreads();
    }
    if (t == 0) {
        float mx = lg[0];
        for (int j = 1; j < 10; j++) mx = fmaxf(mx, lg[j]);
        float se = 0.f;
        for (int j = 0; j < 10; j++) se += expf(lg[j] - mx);
        float lse = logf(se) + mx;
        for (int j = 0; j < 10; j++) lg[j] -= lse;
    }
    __syncthreads();
    if (t < out_size && t < CH) out[t] = e;
    if (t < 10 && CH + t < out_size) out[CH + t] = lg[t];
    for (int idx = 266 + t; idx < out_size; idx += 256) out[idx] = 0.0f;
}

// ---------------- launch ----------------
extern "C" void kernel_launch(void* const* d_in, const int* in_sizes, int n_in,
                              void* d_out, int out_size) {
    const float* x  = (const float*)d_in[0];
    const int*   ei = (const int*)d_in[1];
    const float* w0 = (const float*)d_in[2];
    const float* b0 = (const float*)d_in[3];
    const float* w1 = (const float*)d_in[4];
    const float* b1 = (const float*)d_in[5];
    const float* w2 = (const float*)d_in[6];
    const float* b2 = (const float*)d_in[7];
    const float* p1 = (const float*)d_in[8];
    const float* p2 = (const float*)d_in[9];
    const float* wc = (const float*)d_in[10];
    const float* bc = (const float*)d_in[11];
    float* out = (float*)d_out;
    int E = in_sizes[1] / 2;
    const int n0 = N0, k1 = 2048, k2 = 1024;
    const int NW = CH * CH;

    float *pPart, *pPart2, *pfA, *pfB;
    __nv_bfloat16 *pAtb, *pRb, *pCbb, *pXb, *pWb, *pXwb;
    cudaGetSymbolAddress((void**)&pPart, g_part);
    cudaGetSymbolAddress((void**)&pPart2, g_part2);
    cudaGetSymbolAddress((void**)&pfA, g_fA);
    cudaGetSymbolAddress((void**)&pfB, g_fB);
    cudaGetSymbolAddress((void**)&pAtb, g_Atb);
    cudaGetSymbolAddress((void**)&pRb,  g_Rb);
    cudaGetSymbolAddress((void**)&pCbb, g_Cbb);
    cudaGetSymbolAddress((void**)&pXb,  g_Xb);
    cudaGetSymbolAddress((void**)&pWb,  g_Wb);
    cudaGetSymbolAddress((void**)&pXwb, g_xwb);

    constexpr int SM22 = hgemm_smem<2, 2>();
    constexpr int SM12 = hgemm_smem<1, 2>();
    cudaFuncSetAttribute(k_l0_par, cudaFuncAttributeMaxDynamicSharedMemorySize, SM22);
    cudaFuncSetAttribute(k_l1_par, cudaFuncAttributeMaxDynamicSharedMemorySize, SM22);
    cudaFuncSetAttribute(k_l2b_par, cudaFuncAttributeMaxDynamicSharedMemorySize, SM22);
    cudaFuncSetAttribute(k_hgemm<1, 2, 2, PAIRS_AGG>,
                         cudaFuncAttributeMaxDynamicSharedMemorySize, SM12);

    int fillBlocks = (E + 255) / 256;

    // ---- zero + conversions (one launch) ----
    k_zs<<<16 + (n0 * CH + 3 * NW + 255) / 256, 256>>>(x, w0, w1, w2, pXb, pWb);

    // ---- L0: xw GEMM || edge fill ----
    k_l0_par<<<128 + fillBlocks, 256, SM22>>>(pXb, pWb, pPart, ei, E);
    k_reduceF<<<n0, 256>>>(pPart, pfB, 2, n0, MODE_DINV0, nullptr, nullptr);
    k_agg0<<<n0, 256>>>(pfB, b0, pfA, p1);                      // F0 + score1

    // ---- pool 1 ----
    k_threshcollect<<<1, 1024>>>(n0, k1);
    k_gather_xb<<<(k1 * CH + 255) / 256, 256>>>(pfA, pXb, k1);  // X1 split-2

    // ---- L1: xw GEMM || augment ----
    k_l1_par<<<128 + k1, 256, SM22>>>(pXb, pWb + 2 * NW, pPart, pAtb);
    k_reduce_ds2<<<(k1 * 256 + 255) / 256, 256>>>(pPart, pXwb, 4, k1, 256);
    k_hgemm<1, 2, 2, PAIRS_AGG><<<dim3(2, 16, 4), 256, SM12>>>(pAtb, pXwb, pPart, k1, 256, 512,
                                                                k1, 256, 0, (long)k1 * CH);
    k_reduceF<<<k1, 256>>>(pPart, pfA, 4, k1, MODE_RELU, b1, p2);  // F1 + score2

    // ---- pool 2 + gathers (one launch) ----
    k_threshcollect<<<1, 1024>>>(k1, k2);
    k_l2a_par<<<(k2 * CH + 2 * k2 * k1 + 255) / 256, 256>>>(pfA, pXb, pAtb, pRb, pCbb, k1, k2);

    // ---- L2: xw GEMM || AA GEMM ----
    k_l2b_par<<<256, 256, SM22>>>(pXb, pWb + 4 * NW, pPart, pRb, pCbb, pPart2);
    k_reduce_A2t<<<k2, 256>>>(pPart2, pAtb, k2);                // Atb=A2t + dinv (level 2)
    k_reduce_ds2<<<(k2 * 256 + 255) / 256, 256>>>(pPart, pXwb, 8, k2, 256);
    k_hgemm<1, 2, 2, PAIRS_AGG><<<dim3(2, 8, 8), 256, SM12>>>(pAtb, pXwb, pPart, k2, 256, 128,
                                                               k2, 256, 0, (long)k2 * CH);
    k_reduceF<<<k2, 256>>>(pPart, pfA, 8, k2, MODE_RELU, b2, nullptr);  // F2

    // ---- readout ----
    k_rowsum_f<<<32, 256>>>(pfA, k2);
    k_final<<<1, 256>>>(k2, wc, bc, out, out_size);
}

// round 13
// speedup vs baseline: 1.2881x; 1.2881x over previous
#include <cuda_runtime.h>
#include <cuda_bf16.h>
#include <math.h>

#define N0 4096
#define CH 256
#define DEG 96

#define MODE_DINV0 0
#define MODE_DINV  1
#define MODE_RELU  2

#define PAIRS_X   0x011000
#define PAIRS_AGG 0x0100
#define PAIRS_AA  0x0

// ---------------- scratch ----------------
static __device__ __align__(16) float g_part[2 * 4096 * 256];
static __device__ __align__(16) __nv_bfloat16 g_Atb[2048 * 2048];
static __device__ __align__(16) __nv_bfloat16 g_Rb[1024 * 2048];
static __device__ __align__(16) __nv_bfloat16 g_Cbb[2048 * 1024];
static __device__ __align__(16) __nv_bfloat16 g_Xb[2 * N0 * CH];
static __device__ __align__(16) __nv_bfloat16 g_Wb[3 * 2 * CH * CH];
static __device__ __align__(16) __nv_bfloat16 g_xwb[2 * 2048 * CH];
static __device__ __align__(16) float g_fA[N0 * CH];
static __device__ __align__(16) float g_fB[N0 * CH];
static __device__ __align__(16) float g_fpart[32 * 256];
static __device__ float g_dinv[N0];
static __device__ float g_score[N0];
static __device__ int   g_perm[N0];
static __device__ int   g_csccnt[N0];
static __device__ int   g_srcs[N0 * DEG];
static __device__ int   g_cntdiag[N0];
static __device__ int   g_indeg[N0];

__device__ __forceinline__ unsigned fkey(float f) {
    unsigned u = __float_as_uint(f);
    return (u & 0x80000000u) ? ~u : (u | 0x80000000u);
}

// ---------------- zero + split-2 of x, w0, w1, w2 (merged, no smem) ----------------
__global__ void k_zs(const float* __restrict__ x, const float* __restrict__ w0,
                     const float* __restrict__ w1, const float* __restrict__ w2,
                     __nv_bfloat16* __restrict__ Xb, __nv_bfloat16* __restrict__ Wb) {
    const int nx = N0 * CH;
    const int nw = CH * CH;
    int id = blockIdx.x;
    if (id < 16) {
        int i = id * 256 + threadIdx.x;
        g_csccnt[i] = 0; g_cntdiag[i] = 0; g_indeg[i] = 0;
        return;
    }
    int idx = (id - 16) * 256 + threadIdx.x;
    float v; __nv_bfloat16 *hi, *lo;
    if (idx < nx) {
        v = x[idx];
        hi = Xb + idx; lo = Xb + nx + idx;
    } else {
        int j = idx - nx;
        if (j >= 3 * nw) return;
        int l = j >> 16, o = j & (nw - 1);
        v = (l == 0) ? w0[o] : (l == 1) ? w1[o] : w2[o];
        __nv_bfloat16* base = Wb + (size_t)l * 2 * nw;
        hi = base + o; lo = base + nw + o;
    }
    __nv_bfloat16 h = __float2bfloat16_rn(v);
    *hi = h;
    *lo = __float2bfloat16_rn(v - __bfloat162float(h));
}

__global__ void k_fill(const int* __restrict__ ei, int E) {
    int e = blockIdx.x * blockDim.x + threadIdx.x;
    if (e >= E) return;
    int s = ei[e], d = ei[e + E];
    atomicAdd(&g_indeg[d], 1);
    if (s == d) {
        atomicAdd(&g_cntdiag[s], 1);
    } else {
        int pos = atomicAdd(&g_csccnt[d], 1);
        if (pos < DEG) g_srcs[d * DEG + pos] = s;
    }
}

// ---------------- bf16 HMMA GEMM (R8-proven exact version) ----------------
__device__ __forceinline__ void mma16816(float* d, const unsigned* a, unsigned b0, unsigned b1) {
    asm volatile(
        "mma.sync.aligned.m16n8k16.row.col.f32.bf16.bf16.f32 "
        "{%0,%1,%2,%3}, {%4,%5,%6,%7}, {%8,%9}, {%0,%1,%2,%3};\n"
        : "+f"(d[0]), "+f"(d[1]), "+f"(d[2]), "+f"(d[3])
        : "r"(a[0]), "r"(a[1]), "r"(a[2]), "r"(a[3]), "r"(b0), "r"(b1));
}

template <int NA, int NB>
__host__ __device__ constexpr int hgemm_smem() {
    return 2 * (NA * 128 * 40 * 2 + NB * 16 * 136 * 4);
}

template <int NA, int NB, int NPAIR, int PAIRS>
__global__ void __launch_bounds__(256, 1)
k_hgemm(const __nv_bfloat16* __restrict__ A, const __nv_bfloat16* __restrict__ B,
        float* __restrict__ Cpart, int lda, int ldb, int chunk,
        int M, int N, long aStride, long bStride) {
    extern __shared__ char sm_raw[];
    __nv_bfloat16* Asm = (__nv_bfloat16*)sm_raw;
    unsigned* Bsm = (unsigned*)(sm_raw + 2 * NA * 128 * 40 * 2);

    int tid = threadIdx.x;
    int i0 = blockIdx.y * 128, j0 = blockIdx.x * 128;
    int kbeg = blockIdx.z * chunk, kend = kbeg + chunk;
    int w = tid >> 5, l = tid & 31;
    int wm = w & 3, wn = w >> 2;
    int mb = wm * 32, nb = wn * 64;
    int g = l >> 2, tg = l & 3;

    float acc[2][8][4];
#pragma unroll
    for (int mt = 0; mt < 2; mt++)
#pragma unroll
        for (int j = 0; j < 8; j++)
#pragma unroll
            for (int q = 0; q < 4; q++) acc[mt][j][q] = 0.f;

    int arow = tid >> 1, apart = tid & 1;
    int bkk = tid >> 4, bnseg = tid & 15;

    auto stage = [&](int st, int k0) {
#pragma unroll
        for (int q = 0; q < NA; q++) {
            const uint4* src = (const uint4*)&A[q * aStride + (size_t)(i0 + arow) * lda + k0 + apart * 16];
            uint4* dst = (uint4*)(Asm + ((size_t)(st * NA + q) * 128 + arow) * 40 + apart * 16);
            dst[0] = src[0]; dst[1] = src[1];
        }
#pragma unroll
        for (int p = 0; p < NB; p++) {
            const __nv_bfloat16* Bp = B + p * bStride;
            uint4 lo4 = *(const uint4*)&Bp[(size_t)(k0 + 2 * bkk) * ldb + j0 + bnseg * 8];
            uint4 hi4 = *(const uint4*)&Bp[(size_t)(k0 + 2 * bkk + 1) * ldb + j0 + bnseg * 8];
            unsigned* d = Bsm + ((size_t)(st * NB + p) * 16 + bkk) * 136 + bnseg * 8;
            *(uint4*)d = make_uint4(
                __byte_perm(lo4.x, hi4.x, 0x5410), __byte_perm(lo4.x, hi4.x, 0x7632),
                __byte_perm(lo4.y, hi4.y, 0x5410), __byte_perm(lo4.y, hi4.y, 0x7632));
            *(uint4*)(d + 4) = make_uint4(
                __byte_perm(lo4.z, hi4.z, 0x5410), __byte_perm(lo4.z, hi4.z, 0x7632),
                __byte_perm(lo4.w, hi4.w, 0x5410), __byte_perm(lo4.w, hi4.w, 0x7632));
        }
    };

    stage(0, kbeg);
    __syncthreads();

    for (int k0 = kbeg; k0 < kend; k0 += 32) {
        int cur = ((k0 - kbeg) >> 5) & 1;
        if (k0 + 32 < kend) stage(cur ^ 1, k0 + 32);
#pragma unroll
        for (int ks = 0; ks < 32; ks += 16) {
            unsigned a[NA][2][4];
#pragma unroll
            for (int q = 0; q < NA; q++) {
                const __nv_bfloat16* Aq = Asm + (size_t)(cur * NA + q) * 128 * 40;
#pragma unroll
                for (int mt = 0; mt < 2; mt++) {
                    int r0 = mb + mt * 16 + g;
                    a[q][mt][0] = *(const unsigned*)(Aq + r0 * 40 + ks + tg * 2);
                    a[q][mt][1] = *(const unsigned*)(Aq + (r0 + 8) * 40 + ks + tg * 2);
                    a[q][mt][2] = *(const unsigned*)(Aq + r0 * 40 + ks + tg * 2 + 8);
                    a[q][mt][3] = *(const unsigned*)(Aq + (r0 + 8) * 40 + ks + tg * 2 + 8);
                }
            }
            int kk0 = (ks >> 1) + tg;
#pragma unroll
            for (int p = 0; p < NPAIR; p++) {
                const int ai = (PAIRS >> (8 * p + 4)) & 0xF;
                const int bi = (PAIRS >> (8 * p)) & 0xF;
                const unsigned* Bq = Bsm + (size_t)(cur * NB + bi) * 16 * 136;
#pragma unroll
                for (int j = 0; j < 8; j++) {
                    int n = nb + j * 8 + g;
                    unsigned b0 = Bq[kk0 * 136 + n];
                    unsigned b1 = Bq[(kk0 + 4) * 136 + n];
                    mma16816(acc[0][j], a[ai][0], b0, b1);
                    mma16816(acc[1][j], a[ai][1], b0, b1);
                }
            }
        }
        __syncthreads();
    }
    float* Cp = Cpart + (size_t)blockIdx.z * M * N;
#pragma unroll
    for (int mt = 0; mt < 2; mt++) {
        int gr = i0 + mb + mt * 16 + g;
#pragma unroll
        for (int j = 0; j < 8; j++) {
            int gc = j0 + nb + j * 8 + tg * 2;
            *(float2*)&Cp[(size_t)gr * N + gc] = make_float2(acc[mt][j][0], acc[mt][j][1]);
            *(float2*)&Cp[(size_t)(gr + 8) * N + gc] = make_float2(acc[mt][j][2], acc[mt][j][3]);
        }
    }
}

// ---------------- split-K reduce, one block per output row (N=256) ----------------
__global__ void k_reduceF(const float* __restrict__ Cpart, float* __restrict__ out,
                          int SK, int M, int mode, const float* __restrict__ bias,
                          const float* __restrict__ p) {
    __shared__ float red[256], red2[256];
    int row = blockIdx.x, t = threadIdx.x;
    int idx = row * 256 + t;
    float s = 0.f;
    for (int z = 0; z < SK; z++) s += Cpart[(size_t)z * M * 256 + idx];
    float v;
    if (mode == MODE_DINV0) {
        float deg = (float)g_indeg[row] + ((g_cntdiag[row] == 0) ? 2.0f : 0.0f);
        v = s * rsqrtf(deg);
    } else if (mode == MODE_DINV) {
        v = s * g_dinv[row];
    } else {
        v = fmaxf(g_dinv[row] * s + bias[t], 0.f);
    }
    out[idx] = v;
    if (p != nullptr) {
        float pv = p[t];
        red[t] = v * pv; red2[t] = pv * pv;
        __syncthreads();
        for (int off = 128; off > 0; off >>= 1) {
            if (t < off) { red[t] += red[t + off]; red2[t] += red2[t + off]; }
            __syncthreads();
        }
        if (t == 0) g_score[row] = tanhf(red[0] * rsqrtf(red2[0]));
    }
}

// split-K reduce -> dinv scale -> split-2 bf16 planes
__global__ void k_reduce_ds2(const float* __restrict__ Cpart, __nv_bfloat16* __restrict__ out,
                             int SK, int M, int N) {
    int idx = blockIdx.x * blockDim.x + threadIdx.x;
    if (idx >= M * N) return;
    float s = 0.f;
    for (int z = 0; z < SK; z++) s += Cpart[(size_t)z * M * N + idx];
    float v = s * g_dinv[idx / N];
    __nv_bfloat16 h = __float2bfloat16_rn(v);
    out[idx] = h;
    out[(size_t)M * N + idx] = __float2bfloat16_rn(v - __bfloat162float(h));
}

// split-K reduce for A2^T, one block per row
__global__ void k_reduce_A2t(const float* __restrict__ Cpart, __nv_bfloat16* __restrict__ out,
                             int n) {
    __shared__ float red[256];
    int row = blockIdx.x, t = threadIdx.x;
    float part = 0.f;
    for (int c = t; c < n; c += 256) {
        size_t idx = (size_t)row * n + c;
        float s = Cpart[idx] + Cpart[(size_t)n * n + idx];
        float v = (row == c) ? 2.0f : s;
        out[idx] = __float2bfloat16_rn(v);
        part += v;
    }
    red[t] = part; __syncthreads();
    for (int off = 128; off > 0; off >>= 1) { if (t < off) red[t] += red[t + off]; __syncthreads(); }
    if (t == 0) g_dinv[row] = rsqrtf(red[0]);
}

// ---------------- level-0 aggregation: float4, 4 rows/block, fused score ----------------
__global__ void k_agg0v(const float4* __restrict__ B4, const float* __restrict__ bias,
                        float* __restrict__ out, const float* __restrict__ p) {
    __shared__ float red[256], red2[256];
    int t = threadIdx.x;
    int grp = t >> 6, lane = t & 63;
    int d = blockIdx.x * 4 + grp;
    int cd = g_cntdiag[d];
    float w0 = (cd == 0) ? 2.0f : (float)cd;
    float4 b = B4[(size_t)d * 64 + lane];
    float4 a0 = make_float4(w0 * b.x, w0 * b.y, w0 * b.z, w0 * b.w);
    float4 a1 = make_float4(0.f, 0.f, 0.f, 0.f);
    int cnt = g_csccnt[d];
    const int* src = &g_srcs[d * DEG];
    int e = 0;
    for (; e + 2 <= cnt; e += 2) {
        int s0 = __ldg(&src[e]), s1 = __ldg(&src[e + 1]);
        float4 v0 = B4[(size_t)s0 * 64 + lane];
        float4 v1 = B4[(size_t)s1 * 64 + lane];
        a0.x += v0.x; a0.y += v0.y; a0.z += v0.z; a0.w += v0.w;
        a1.x += v1.x; a1.y += v1.y; a1.z += v1.z; a1.w += v1.w;
    }
    if (e < cnt) {
        int s0 = __ldg(&src[e]);
        float4 v0 = B4[(size_t)s0 * 64 + lane];
        a0.x += v0.x; a0.y += v0.y; a0.z += v0.z; a0.w += v0.w;
    }
    float deg = (float)g_indeg[d] + ((cd == 0) ? 2.0f : 0.0f);
    float di = rsqrtf(deg);
    float4 b4 = ((const float4*)bias)[lane];
    float4 v;
    v.x = fmaxf(di * (a0.x + a1.x) + b4.x, 0.f);
    v.y = fmaxf(di * (a0.y + a1.y) + b4.y, 0.f);
    v.z = fmaxf(di * (a0.z + a1.z) + b4.z, 0.f);
    v.w = fmaxf(di * (a0.w + a1.w) + b4.w, 0.f);
    ((float4*)out)[(size_t)d * 64 + lane] = v;
    float4 p4 = ((const float4*)p)[lane];
    red[t]  = v.x * p4.x + v.y * p4.y + v.z * p4.z + v.w * p4.w;
    red2[t] = p4.x * p4.x + p4.y * p4.y + p4.z * p4.z + p4.w * p4.w;
    __syncthreads();
#pragma unroll
    for (int off = 32; off > 0; off >>= 1) {
        if (lane < off) { red[t] += red[t + off]; red2[t] += red2[t + off]; }
        __syncthreads();
    }
    if (lane == 0) g_score[d] = tanhf(red[t] * rsqrtf(red2[t]));
}

// ---------------- level-1 augment (R8 static-smem version) ----------------
__global__ void k_augmentT(__nv_bfloat16* __restrict__ Atb) {
    __shared__ float s[N0];
    __shared__ int sp[2048];
    __shared__ float red[256];
    int r = blockIdx.x, t = threadIdx.x;
    for (int c = t; c < N0; c += 256) s[c] = 0.f;
    for (int c = t; c < 2048; c += 256) sp[c] = g_perm[c];
    __syncthreads();
    int i = sp[r];
    int lane = t & 31, w = t >> 5;
    int cnt = g_csccnt[i];
    const int* isrc = &g_srcs[i * DEG];
    for (int e = w; e < cnt; e += 8) {
        int kc = isrc[e];
        if (lane == 0) atomicAdd(&s[kc], 2.0f);
        int cnt2 = g_csccnt[kc];
        const int* ksrc = &g_srcs[kc * DEG];
        for (int f = lane; f < cnt2; f += 32) atomicAdd(&s[ksrc[f]], 1.0f);
    }
    __syncthreads();
    __nv_bfloat16* row = Atb + (size_t)r * 2048;
    float part = 0.f;
    for (int c = t; c < 2048; c += 256) {
        float v = (c == r) ? 2.0f : s[sp[c]];
        row[c] = __float2bfloat16_rn(v);
        part += v;
    }
    red[t] = part; __syncthreads();
    for (int off = 128; off > 0; off >>= 1) { if (t < off) red[t] += red[t + off]; __syncthreads(); }
    if (t == 0) g_dinv[r] = rsqrtf(red[0]);
}

// ---------------- top-k threshold + collect ----------------
__global__ void k_threshcollect(int n, int k) {
    __shared__ unsigned u[N0];
    __shared__ int sc[2];
    int t = threadIdx.x;
    int per = n >> 10;
    for (int i = t; i < n; i += 1024) u[i] = fkey(g_score[i]);
    __syncthreads();
    unsigned thr = 0;
    for (int bit = 31; bit >= 0; --bit) {
        unsigned cand = thr | (1u << bit);
        int c = 0;
        for (int j = 0; j < per; j++)
            c += __syncthreads_count(u[j * 1024 + t] >= cand);
        if (c >= k) thr = cand;
    }
    int cg = 0;
    for (int j = 0; j < per; j++)
        cg += __syncthreads_count(u[j * 1024 + t] > thr);
    if (t == 0) { sc[0] = 0; sc[1] = 0; }
    __syncthreads();
    for (int i = t; i < n; i += 1024) {
        unsigned v = u[i];
        if (v > thr) {
            int p = atomicAdd(&sc[0], 1);
            g_perm[p] = i;
        } else if (v == thr) {
            int p = atomicAdd(&sc[1], 1);
            int pos = cg + p;
            if (pos < k) g_perm[pos] = i;
        }
    }
}

// gather + gate + split-2 bf16 (level 1)
__global__ void k_gather_xb(const float* __restrict__ src, __nv_bfloat16* __restrict__ dst, int k) {
    int idx = blockIdx.x * blockDim.x + threadIdx.x;
    if (idx >= k * CH) return;
    int r = idx >> 8;
    int p = g_perm[r];
    float v = src[(size_t)p * CH + (idx & 255)] * g_score[p];
    __nv_bfloat16 h = __float2bfloat16_rn(v);
    dst[idx] = h;
    dst[(size_t)k * CH + idx] = __float2bfloat16_rn(v - __bfloat162float(h));
}

// fused level-2 gathers: X gather + R + C
__global__ void k_l2a_par(const float* __restrict__ src, __nv_bfloat16* __restrict__ dstX,
                          const __nv_bfloat16* __restrict__ At,
                          __nv_bfloat16* __restrict__ R, __nv_bfloat16* __restrict__ Cb,
                          int kold, int kn) {
    int idx = blockIdx.x * blockDim.x + threadIdx.x;
    int totx = kn * CH;
    int tot = kn * kold;
    if (idx < totx) {
        int r = idx >> 8;
        int p = g_perm[r];
        float v = src[(size_t)p * CH + (idx & 255)] * g_score[p];
        __nv_bfloat16 h = __float2bfloat16_rn(v);
        dstX[idx] = h;
        dstX[(size_t)kn * CH + idx] = __float2bfloat16_rn(v - __bfloat162float(h));
        return;
    }
    int j0 = idx - totx;
    if (j0 < tot) {
        int r = j0 / kold, k = j0 - r * kold;
        int p = g_perm[r];
        R[j0] = (k == p) ? __float2bfloat16_rn(1.0f) : At[(size_t)p * kold + k];
    } else if (j0 < 2 * tot) {
        int j = j0 - tot;
        int k = j / kn, c = j - k * kn;
        int p = g_perm[c];
        Cb[j] = (k == p) ? __float2bfloat16_rn(1.0f) : At[(size_t)k * kold + p];
    }
}

// ---------------- final readout ----------------
__global__ void k_rowsum_f(const float* __restrict__ F, int n) {
    int t = threadIdx.x;
    int rows = n / 32;
    float s = 0.f;
    int r0 = blockIdx.x * rows;
    for (int r = r0; r < r0 + rows; r++) s += F[(size_t)r * CH + t];
    g_fpart[blockIdx.x * 256 + t] = s;
}

__global__ void k_final(int n, const float* __restrict__ wc,
                        const float* __restrict__ bc, float* __restrict__ out, int out_size) {
    __shared__ float red[256];
    __shared__ float lg[16];
    int t = threadIdx.x;
    float s = 0.f;
#pragma unroll
    for (int b = 0; b < 32; b++) s += g_fpart[b * 256 + t];
    float mv = s / (float)n;
    red[t] = mv * mv; __syncthreads();
    for (int off = 128; off > 0; off >>= 1) { if (t < off) red[t] += red[t + off]; __syncthreads(); }
    float nrm = fmaxf(sqrtf(red[0]), 1e-12f);
    __syncthreads();
    float e = mv / nrm;
    for (int j = 0; j < 10; j++) {
        red[t] = e * wc[j * CH + t]; __syncthreads();
        for (int off = 128; off > 0; off >>= 1) { if (t < off) red[t] += red[t + off]; __syncthreads(); }
        if (t == 0) lg[j] = red[0] + bc[j];
        __syncthreads();
    }
    if (t == 0) {
        float mx = lg[0];
        for (int j = 1; j < 10; j++) mx = fmaxf(mx, lg[j]);
        float se = 0.f;
        for (int j = 0; j < 10; j++) se += expf(lg[j] - mx);
        float lse = logf(se) + mx;
        for (int j = 0; j < 10; j++) lg[j] -= lse;
    }
    __syncthreads();
    if (t < out_size && t < CH) out[t] = e;
    if (t < 10 && CH + t < out_size) out[CH + t] = lg[t];
    for (int idx = 266 + t; idx < out_size; idx += 256) out[idx] = 0.0f;
}

// ---------------- launch ----------------
extern "C" void kernel_launch(void* const* d_in, const int* in_sizes, int n_in,
                              void* d_out, int out_size) {
    const float* x  = (const float*)d_in[0];
    const int*   ei = (const int*)d_in[1];
    const float* w0 = (const float*)d_in[2];
    const float* b0 = (const float*)d_in[3];
    const float* w1 = (const float*)d_in[4];
    const float* b1 = (const float*)d_in[5];
    const float* w2 = (const float*)d_in[6];
    const float* b2 = (const float*)d_in[7];
    const float* p1 = (const float*)d_in[8];
    const float* p2 = (const float*)d_in[9];
    const float* wc = (const float*)d_in[10];
    const float* bc = (const float*)d_in[11];
    float* out = (float*)d_out;
    int E = in_sizes[1] / 2;
    const int n0 = N0, k1 = 2048, k2 = 1024;
    const int NW = CH * CH;

    float *pPart, *pfA, *pfB;
    __nv_bfloat16 *pAtb, *pRb, *pCbb, *pXb, *pWb, *pXwb;
    cudaGetSymbolAddress((void**)&pPart, g_part);
    cudaGetSymbolAddress((void**)&pfA, g_fA);
    cudaGetSymbolAddress((void**)&pfB, g_fB);
    cudaGetSymbolAddress((void**)&pAtb, g_Atb);
    cudaGetSymbolAddress((void**)&pRb,  g_Rb);
    cudaGetSymbolAddress((void**)&pCbb, g_Cbb);
    cudaGetSymbolAddress((void**)&pXb,  g_Xb);
    cudaGetSymbolAddress((void**)&pWb,  g_Wb);
    cudaGetSymbolAddress((void**)&pXwb, g_xwb);

    constexpr int SM22 = hgemm_smem<2, 2>();
    constexpr int SM12 = hgemm_smem<1, 2>();
    constexpr int SM11 = hgemm_smem<1, 1>();
    cudaFuncSetAttribute(k_hgemm<2, 2, 3, PAIRS_X>,
                         cudaFuncAttributeMaxDynamicSharedMemorySize, SM22);
    cudaFuncSetAttribute(k_hgemm<1, 2, 2, PAIRS_AGG>,
                         cudaFuncAttributeMaxDynamicSharedMemorySize, SM12);
    cudaFuncSetAttribute(k_hgemm<1, 1, 1, PAIRS_AA>,
                         cudaFuncAttributeMaxDynamicSharedMemorySize, SM11);

    // ---- graph build + conversions ----
    k_zs<<<16 + (n0 * CH + 3 * NW + 255) / 256, 256>>>(x, w0, w1, w2, pXb, pWb);
    k_fill<<<(E + 255) / 256, 256>>>(ei, E);

    // ---- GCN level 0 ----
    k_hgemm<2, 2, 3, PAIRS_X><<<dim3(2, 32, 2), 256, SM22>>>(pXb, pWb, pPart, 256, 256, 128,
                                                              n0, 256, (long)n0 * CH, (long)NW);
    k_reduceF<<<n0, 256>>>(pPart, pfB, 2, n0, MODE_DINV0, nullptr, nullptr);
    k_agg0v<<<n0 / 4, 256>>>((const float4*)pfB, b0, pfA, p1);   // F0 + score1

    // ---- pool 1 ----
    k_threshcollect<<<1, 1024>>>(n0, k1);
    k_gather_xb<<<(k1 * CH + 255) / 256, 256>>>(pfA, pXb, k1);

    // ---- augment level 1 ----
    k_augmentT<<<k1, 256>>>(pAtb);

    // ---- GCN level 1 ----
    k_hgemm<2, 2, 3, PAIRS_X><<<dim3(2, 16, 4), 256, SM22>>>(pXb, pWb + 2 * NW, pPart, 256, 256, 64,
                                                              k1, 256, (long)k1 * CH, (long)NW);
    k_reduce_ds2<<<(k1 * 256 + 255) / 256, 256>>>(pPart, pXwb, 4, k1, 256);
    k_hgemm<1, 2, 2, PAIRS_AGG><<<dim3(2, 16, 4), 256, SM12>>>(pAtb, pXwb, pPart, k1, 256, 512,
                                                                k1, 256, 0, (long)k1 * CH);
    k_reduceF<<<k1, 256>>>(pPart, pfA, 4, k1, MODE_RELU, b1, p2);  // F1 + score2

    // ---- pool 2 + fused gathers ----
    k_threshcollect<<<1, 1024>>>(k1, k2);
    k_l2a_par<<<(k2 * CH + 2 * k2 * k1 + 255) / 256, 256>>>(pfA, pXb, pAtb, pRb, pCbb, k1, k2);

    // ---- augment level 2 (GEMM) ----
    k_hgemm<1, 1, 1, PAIRS_AA><<<dim3(8, 8, 2), 256, SM11>>>(pRb, pCbb, pPart, k1, k2, 1024,
                                                              k2, k2, 0, 0);
    k_reduce_A2t<<<k2, 256>>>(pPart, pAtb, k2);                 // Atb=A2t + dinv

    // ---- GCN level 2 ----
    k_hgemm<2, 2, 3, PAIRS_X><<<dim3(2, 8, 8), 256, SM22>>>(pXb, pWb + 4 * NW, pPart, 256, 256, 32,
                                                             k2, 256, (long)k2 * CH, (long)NW);
    k_reduce_ds2<<<(k2 * 256 + 255) / 256, 256>>>(pPart, pXwb, 8, k2, 256);
    k_hgemm<1, 2, 2, PAIRS_AGG><<<dim3(2, 8, 8), 256, SM12>>>(pAtb, pXwb, pPart, k2, 256, 128,
                                                               k2, 256, 0, (long)k2 * CH);
    k_reduceF<<<k2, 256>>>(pPart, pfA, 8, k2, MODE_RELU, b2, nullptr);  // F2

    // ---- readout ----
    k_rowsum_f<<<32, 256>>>(pfA, k2);
    k_final<<<1, 256>>>(k2, wc, bc, out, out_size);
}

// round 14
// speedup vs baseline: 1.3786x; 1.0703x over previous
#include <cuda_runtime.h>
#include <cuda_bf16.h>
#include <math.h>

#define N0 4096
#define CH 256
#define DEG 96

#define MODE_DINV0 0
#define MODE_DINV  1
#define MODE_RELU  2

#define PAIRS_X   0x011000
#define PAIRS_AGG 0x0100
#define PAIRS_AA  0x0

// ---------------- scratch ----------------
static __device__ __align__(16) float g_part[2 * 4096 * 256];
static __device__ __align__(16) __nv_bfloat16 g_Atb[2048 * 2048];
static __device__ __align__(16) __nv_bfloat16 g_Rb[1024 * 2048];
static __device__ __align__(16) __nv_bfloat16 g_Cbb[2048 * 1024];
static __device__ __align__(16) __nv_bfloat16 g_Xb[2 * N0 * CH];
static __device__ __align__(16) __nv_bfloat16 g_Wb[3 * 2 * CH * CH];
static __device__ __align__(16) __nv_bfloat16 g_xwb[2 * 2048 * CH];
static __device__ __align__(16) float g_fA[N0 * CH];
static __device__ __align__(16) float g_fB[N0 * CH];
static __device__ __align__(16) float g_fpart[32 * 256];
static __device__ float g_dinv[N0];
static __device__ float g_score[N0];
static __device__ int   g_perm[N0];
static __device__ int   g_csccnt[N0];
static __device__ int   g_srcs[N0 * DEG];
static __device__ int   g_cntdiag[N0];
static __device__ int   g_indeg[N0];

__device__ __forceinline__ unsigned fkey(float f) {
    unsigned u = __float_as_uint(f);
    return (u & 0x80000000u) ? ~u : (u | 0x80000000u);
}

__device__ __forceinline__ uint2 pack4bf(float a, float b, float c, float d) {
    __nv_bfloat162 lo = __floats2bfloat162_rn(a, b);
    __nv_bfloat162 hi = __floats2bfloat162_rn(c, d);
    return make_uint2(*(unsigned*)&lo, *(unsigned*)&hi);
}

// ---------------- zero + split-2 of x, w0, w1, w2 ----------------
__global__ void k_zs(const float* __restrict__ x, const float* __restrict__ w0,
                     const float* __restrict__ w1, const float* __restrict__ w2,
                     __nv_bfloat16* __restrict__ Xb, __nv_bfloat16* __restrict__ Wb) {
    const int nx = N0 * CH;
    const int nw = CH * CH;
    int id = blockIdx.x;
    if (id < 16) {
        int i = id * 256 + threadIdx.x;
        g_csccnt[i] = 0; g_cntdiag[i] = 0; g_indeg[i] = 0;
        return;
    }
    int idx = (id - 16) * 256 + threadIdx.x;
    float v; __nv_bfloat16 *hi, *lo;
    if (idx < nx) {
        v = x[idx];
        hi = Xb + idx; lo = Xb + nx + idx;
    } else {
        int j = idx - nx;
        if (j >= 3 * nw) return;
        int l = j >> 16, o = j & (nw - 1);
        v = (l == 0) ? w0[o] : (l == 1) ? w1[o] : w2[o];
        __nv_bfloat16* base = Wb + (size_t)l * 2 * nw;
        hi = base + o; lo = base + nw + o;
    }
    __nv_bfloat16 h = __float2bfloat16_rn(v);
    *hi = h;
    *lo = __float2bfloat16_rn(v - __bfloat162float(h));
}

__global__ void k_fill(const int* __restrict__ ei, int E) {
    int e = blockIdx.x * blockDim.x + threadIdx.x;
    if (e >= E) return;
    int s = ei[e], d = ei[e + E];
    atomicAdd(&g_indeg[d], 1);
    if (s == d) {
        atomicAdd(&g_cntdiag[s], 1);
    } else {
        int pos = atomicAdd(&g_csccnt[d], 1);
        if (pos < DEG) g_srcs[d * DEG + pos] = s;
    }
}

// ---------------- bf16 HMMA GEMM (R8-proven) ----------------
__device__ __forceinline__ void mma16816(float* d, const unsigned* a, unsigned b0, unsigned b1) {
    asm volatile(
        "mma.sync.aligned.m16n8k16.row.col.f32.bf16.bf16.f32 "
        "{%0,%1,%2,%3}, {%4,%5,%6,%7}, {%8,%9}, {%0,%1,%2,%3};\n"
        : "+f"(d[0]), "+f"(d[1]), "+f"(d[2]), "+f"(d[3])
        : "r"(a[0]), "r"(a[1]), "r"(a[2]), "r"(a[3]), "r"(b0), "r"(b1));
}

template <int NA, int NB>
__host__ __device__ constexpr int hgemm_smem() {
    return 2 * (NA * 128 * 40 * 2 + NB * 16 * 136 * 4);
}

template <int NA, int NB, int NPAIR, int PAIRS>
__global__ void __launch_bounds__(256, 1)
k_hgemm(const __nv_bfloat16* __restrict__ A, const __nv_bfloat16* __restrict__ B,
        float* __restrict__ Cpart, int lda, int ldb, int chunk,
        int M, int N, long aStride, long bStride) {
    extern __shared__ char sm_raw[];
    __nv_bfloat16* Asm = (__nv_bfloat16*)sm_raw;
    unsigned* Bsm = (unsigned*)(sm_raw + 2 * NA * 128 * 40 * 2);

    int tid = threadIdx.x;
    int i0 = blockIdx.y * 128, j0 = blockIdx.x * 128;
    int kbeg = blockIdx.z * chunk, kend = kbeg + chunk;
    int w = tid >> 5, l = tid & 31;
    int wm = w & 3, wn = w >> 2;
    int mb = wm * 32, nb = wn * 64;
    int g = l >> 2, tg = l & 3;

    float acc[2][8][4];
#pragma unroll
    for (int mt = 0; mt < 2; mt++)
#pragma unroll
        for (int j = 0; j < 8; j++)
#pragma unroll
            for (int q = 0; q < 4; q++) acc[mt][j][q] = 0.f;

    int arow = tid >> 1, apart = tid & 1;
    int bkk = tid >> 4, bnseg = tid & 15;

    auto stage = [&](int st, int k0) {
#pragma unroll
        for (int q = 0; q < NA; q++) {
            const uint4* src = (const uint4*)&A[q * aStride + (size_t)(i0 + arow) * lda + k0 + apart * 16];
            uint4* dst = (uint4*)(Asm + ((size_t)(st * NA + q) * 128 + arow) * 40 + apart * 16);
            dst[0] = src[0]; dst[1] = src[1];
        }
#pragma unroll
        for (int p = 0; p < NB; p++) {
            const __nv_bfloat16* Bp = B + p * bStride;
            uint4 lo4 = *(const uint4*)&Bp[(size_t)(k0 + 2 * bkk) * ldb + j0 + bnseg * 8];
            uint4 hi4 = *(const uint4*)&Bp[(size_t)(k0 + 2 * bkk + 1) * ldb + j0 + bnseg * 8];
            unsigned* d = Bsm + ((size_t)(st * NB + p) * 16 + bkk) * 136 + bnseg * 8;
            *(uint4*)d = make_uint4(
                __byte_perm(lo4.x, hi4.x, 0x5410), __byte_perm(lo4.x, hi4.x, 0x7632),
                __byte_perm(lo4.y, hi4.y, 0x5410), __byte_perm(lo4.y, hi4.y, 0x7632));
            *(uint4*)(d + 4) = make_uint4(
                __byte_perm(lo4.z, hi4.z, 0x5410), __byte_perm(lo4.z, hi4.z, 0x7632),
                __byte_perm(lo4.w, hi4.w, 0x5410), __byte_perm(lo4.w, hi4.w, 0x7632));
        }
    };

    stage(0, kbeg);
    __syncthreads();

    for (int k0 = kbeg; k0 < kend; k0 += 32) {
        int cur = ((k0 - kbeg) >> 5) & 1;
        if (k0 + 32 < kend) stage(cur ^ 1, k0 + 32);
#pragma unroll
        for (int ks = 0; ks < 32; ks += 16) {
            unsigned a[NA][2][4];
#pragma unroll
            for (int q = 0; q < NA; q++) {
                const __nv_bfloat16* Aq = Asm + (size_t)(cur * NA + q) * 128 * 40;
#pragma unroll
                for (int mt = 0; mt < 2; mt++) {
                    int r0 = mb + mt * 16 + g;
                    a[q][mt][0] = *(const unsigned*)(Aq + r0 * 40 + ks + tg * 2);
                    a[q][mt][1] = *(const unsigned*)(Aq + (r0 + 8) * 40 + ks + tg * 2);
                    a[q][mt][2] = *(const unsigned*)(Aq + r0 * 40 + ks + tg * 2 + 8);
                    a[q][mt][3] = *(const unsigned*)(Aq + (r0 + 8) * 40 + ks + tg * 2 + 8);
                }
            }
            int kk0 = (ks >> 1) + tg;
#pragma unroll
            for (int p = 0; p < NPAIR; p++) {
                const int ai = (PAIRS >> (8 * p + 4)) & 0xF;
                const int bi = (PAIRS >> (8 * p)) & 0xF;
                const unsigned* Bq = Bsm + (size_t)(cur * NB + bi) * 16 * 136;
#pragma unroll
                for (int j = 0; j < 8; j++) {
                    int n = nb + j * 8 + g;
                    unsigned b0 = Bq[kk0 * 136 + n];
                    unsigned b1 = Bq[(kk0 + 4) * 136 + n];
                    mma16816(acc[0][j], a[ai][0], b0, b1);
                    mma16816(acc[1][j], a[ai][1], b0, b1);
                }
            }
        }
        __syncthreads();
    }
    float* Cp = Cpart + (size_t)blockIdx.z * M * N;
#pragma unroll
    for (int mt = 0; mt < 2; mt++) {
        int gr = i0 + mb + mt * 16 + g;
#pragma unroll
        for (int j = 0; j < 8; j++) {
            int gc = j0 + nb + j * 8 + tg * 2;
            *(float2*)&Cp[(size_t)gr * N + gc] = make_float2(acc[mt][j][0], acc[mt][j][1]);
            *(float2*)&Cp[(size_t)(gr + 8) * N + gc] = make_float2(acc[mt][j][2], acc[mt][j][3]);
        }
    }
}

// ---------------- vectorized split-K reduce: 4 rows/block, float4 ----------------
__global__ void k_reduceFv(const float4* __restrict__ Cpart4, float4* __restrict__ out4,
                           int SK, int M, int mode, const float4* __restrict__ bias4,
                           const float4* __restrict__ p4arr) {
    __shared__ float red[256], red2[256];
    int t = threadIdx.x;
    int grp = t >> 6, lane = t & 63;
    int row = blockIdx.x * 4 + grp;
    size_t idx = (size_t)row * 64 + lane;
    float4 s = Cpart4[idx];
    for (int z = 1; z < SK; z++) {
        float4 c = Cpart4[(size_t)z * M * 64 + idx];
        s.x += c.x; s.y += c.y; s.z += c.z; s.w += c.w;
    }
    float4 v;
    if (mode == MODE_DINV0) {
        float deg = (float)g_indeg[row] + ((g_cntdiag[row] == 0) ? 2.0f : 0.0f);
        float di = rsqrtf(deg);
        v = make_float4(s.x * di, s.y * di, s.z * di, s.w * di);
    } else if (mode == MODE_DINV) {
        float di = g_dinv[row];
        v = make_float4(s.x * di, s.y * di, s.z * di, s.w * di);
    } else {
        float di = g_dinv[row];
        float4 b = bias4[lane];
        v.x = fmaxf(di * s.x + b.x, 0.f);
        v.y = fmaxf(di * s.y + b.y, 0.f);
        v.z = fmaxf(di * s.z + b.z, 0.f);
        v.w = fmaxf(di * s.w + b.w, 0.f);
    }
    out4[idx] = v;
    if (p4arr != nullptr) {
        float4 p = p4arr[lane];
        red[t]  = v.x * p.x + v.y * p.y + v.z * p.z + v.w * p.w;
        red2[t] = p.x * p.x + p.y * p.y + p.z * p.z + p.w * p.w;
        __syncthreads();
#pragma unroll
        for (int off = 32; off > 0; off >>= 1) {
            if (lane < off) { red[t] += red[t + off]; red2[t] += red2[t + off]; }
            __syncthreads();
        }
        if (lane == 0) g_score[row] = tanhf(red[t] * rsqrtf(red2[t]));
    }
}

// vectorized split-K reduce -> dinv -> split-2 bf16 planes
__global__ void k_reduce_ds2v(const float4* __restrict__ Cpart4, __nv_bfloat16* __restrict__ out,
                              int SK, int M, int N) {
    int q = blockIdx.x * blockDim.x + threadIdx.x;      // unit = 4 elements
    int tot4 = M * N / 4;
    if (q >= tot4) return;
    float4 s = Cpart4[q];
    for (int z = 1; z < SK; z++) {
        float4 c = Cpart4[(size_t)z * tot4 + q];
        s.x += c.x; s.y += c.y; s.z += c.z; s.w += c.w;
    }
    int row = (q * 4) / N;
    float di = g_dinv[row];
    float vx = s.x * di, vy = s.y * di, vz = s.z * di, vw = s.w * di;
    float hx = __bfloat162float(__float2bfloat16_rn(vx));
    float hy = __bfloat162float(__float2bfloat16_rn(vy));
    float hz = __bfloat162float(__float2bfloat16_rn(vz));
    float hw = __bfloat162float(__float2bfloat16_rn(vw));
    *(uint2*)(out + (size_t)q * 4) = pack4bf(vx, vy, vz, vw);
    *(uint2*)(out + (size_t)M * N + (size_t)q * 4) = pack4bf(vx - hx, vy - hy, vz - hz, vw - hw);
}

// vectorized A2^T reduce: one block/row, float4 loads, 4-bf16 stores, rowsum->dinv
__global__ void k_reduce_A2tv(const float4* __restrict__ Cpart4, __nv_bfloat16* __restrict__ out,
                              int n) {
    __shared__ float red[256];
    int row = blockIdx.x, t = threadIdx.x;
    int n4 = n / 4;
    int tot4 = n * n / 4;
    float part = 0.f;
    for (int c4 = t; c4 < n4; c4 += 256) {
        size_t idx = (size_t)row * n4 + c4;
        float4 a = Cpart4[idx];
        float4 b = Cpart4[(size_t)tot4 + idx];
        float vx = a.x + b.x, vy = a.y + b.y, vz = a.z + b.z, vw = a.w + b.w;
        int c = c4 * 4;
        if (row >= c && row < c + 4) {
            if (row == c)     vx = 2.0f;
            if (row == c + 1) vy = 2.0f;
            if (row == c + 2) vz = 2.0f;
            if (row == c + 3) vw = 2.0f;
        }
        *(uint2*)(out + (size_t)row * n + c) = pack4bf(vx, vy, vz, vw);
        part += vx + vy + vz + vw;
    }
    red[t] = part; __syncthreads();
    for (int off = 128; off > 0; off >>= 1) { if (t < off) red[t] += red[t + off]; __syncthreads(); }
    if (t == 0) g_dinv[row] = rsqrtf(red[0]);
}

// ---------------- level-0 aggregation: float4, 4 rows/block, fused score ----------------
__global__ void k_agg0v(const float4* __restrict__ B4, const float* __restrict__ bias,
                        float* __restrict__ out, const float* __restrict__ p) {
    __shared__ float red[256], red2[256];
    int t = threadIdx.x;
    int grp = t >> 6, lane = t & 63;
    int d = blockIdx.x * 4 + grp;
    int cd = g_cntdiag[d];
    float w0 = (cd == 0) ? 2.0f : (float)cd;
    float4 b = B4[(size_t)d * 64 + lane];
    float4 a0 = make_float4(w0 * b.x, w0 * b.y, w0 * b.z, w0 * b.w);
    float4 a1 = make_float4(0.f, 0.f, 0.f, 0.f);
    int cnt = g_csccnt[d];
    const int* src = &g_srcs[d * DEG];
    int e = 0;
    for (; e + 2 <= cnt; e += 2) {
        int s0 = __ldg(&src[e]), s1 = __ldg(&src[e + 1]);
        float4 v0 = B4[(size_t)s0 * 64 + lane];
        float4 v1 = B4[(size_t)s1 * 64 + lane];
        a0.x += v0.x; a0.y += v0.y; a0.z += v0.z; a0.w += v0.w;
        a1.x += v1.x; a1.y += v1.y; a1.z += v1.z; a1.w += v1.w;
    }
    if (e < cnt) {
        int s0 = __ldg(&src[e]);
        float4 v0 = B4[(size_t)s0 * 64 + lane];
        a0.x += v0.x; a0.y += v0.y; a0.z += v0.z; a0.w += v0.w;
    }
    float deg = (float)g_indeg[d] + ((cd == 0) ? 2.0f : 0.0f);
    float di = rsqrtf(deg);
    float4 b4 = ((const float4*)bias)[lane];
    float4 v;
    v.x = fmaxf(di * (a0.x + a1.x) + b4.x, 0.f);
    v.y = fmaxf(di * (a0.y + a1.y) + b4.y, 0.f);
    v.z = fmaxf(di * (a0.z + a1.z) + b4.z, 0.f);
    v.w = fmaxf(di * (a0.w + a1.w) + b4.w, 0.f);
    ((float4*)out)[(size_t)d * 64 + lane] = v;
    float4 p4 = ((const float4*)p)[lane];
    red[t]  = v.x * p4.x + v.y * p4.y + v.z * p4.z + v.w * p4.w;
    red2[t] = p4.x * p4.x + p4.y * p4.y + p4.z * p4.z + p4.w * p4.w;
    __syncthreads();
#pragma unroll
    for (int off = 32; off > 0; off >>= 1) {
        if (lane < off) { red[t] += red[t + off]; red2[t] += red2[t + off]; }
        __syncthreads();
    }
    if (lane == 0) g_score[d] = tanhf(red[t] * rsqrtf(red2[t]));
}

// ---------------- level-1 augment ----------------
__global__ void k_augmentT(__nv_bfloat16* __restrict__ Atb) {
    __shared__ float s[N0];
    __shared__ int sp[2048];
    __shared__ float red[256];
    int r = blockIdx.x, t = threadIdx.x;
    for (int c = t; c < N0; c += 256) s[c] = 0.f;
    for (int c = t; c < 2048; c += 256) sp[c] = g_perm[c];
    __syncthreads();
    int i = sp[r];
    int lane = t & 31, w = t >> 5;
    int cnt = g_csccnt[i];
    const int* isrc = &g_srcs[i * DEG];
    for (int e = w; e < cnt; e += 8) {
        int kc = isrc[e];
        if (lane == 0) atomicAdd(&s[kc], 2.0f);
        int cnt2 = g_csccnt[kc];
        const int* ksrc = &g_srcs[kc * DEG];
        for (int f = lane; f < cnt2; f += 32) atomicAdd(&s[ksrc[f]], 1.0f);
    }
    __syncthreads();
    __nv_bfloat16* row = Atb + (size_t)r * 2048;
    float part = 0.f;
    for (int c = t; c < 2048; c += 256) {
        float v = (c == r) ? 2.0f : s[sp[c]];
        row[c] = __float2bfloat16_rn(v);
        part += v;
    }
    red[t] = part; __syncthreads();
    for (int off = 128; off > 0; off >>= 1) { if (t < off) red[t] += red[t + off]; __syncthreads(); }
    if (t == 0) g_dinv[r] = rsqrtf(red[0]);
}

// ---------------- top-k threshold + collect ----------------
__global__ void k_threshcollect(int n, int k) {
    __shared__ unsigned u[N0];
    __shared__ int sc[2];
    int t = threadIdx.x;
    int per = n >> 10;
    for (int i = t; i < n; i += 1024) u[i] = fkey(g_score[i]);
    __syncthreads();
    unsigned thr = 0;
    for (int bit = 31; bit >= 0; --bit) {
        unsigned cand = thr | (1u << bit);
        int c = 0;
        for (int j = 0; j < per; j++)
            c += __syncthreads_count(u[j * 1024 + t] >= cand);
        if (c >= k) thr = cand;
    }
    int cg = 0;
    for (int j = 0; j < per; j++)
        cg += __syncthreads_count(u[j * 1024 + t] > thr);
    if (t == 0) { sc[0] = 0; sc[1] = 0; }
    __syncthreads();
    for (int i = t; i < n; i += 1024) {
        unsigned v = u[i];
        if (v > thr) {
            int p = atomicAdd(&sc[0], 1);
            g_perm[p] = i;
        } else if (v == thr) {
            int p = atomicAdd(&sc[1], 1);
            int pos = cg + p;
            if (pos < k) g_perm[pos] = i;
        }
    }
}

// vectorized gather + gate + split-2 (level 1)
__global__ void k_gather_xbv(const float4* __restrict__ src4, __nv_bfloat16* __restrict__ dst, int k) {
    int q = blockIdx.x * blockDim.x + threadIdx.x;      // unit = 4 channels
    int tot4 = k * 64;
    if (q >= tot4) return;
    int r = q >> 6, c4 = q & 63;
    int p = g_perm[r];
    float sc = g_score[p];
    float4 v = src4[(size_t)p * 64 + c4];
    float vx = v.x * sc, vy = v.y * sc, vz = v.z * sc, vw = v.w * sc;
    float hx = __bfloat162float(__float2bfloat16_rn(vx));
    float hy = __bfloat162float(__float2bfloat16_rn(vy));
    float hz = __bfloat162float(__float2bfloat16_rn(vz));
    float hw = __bfloat162float(__float2bfloat16_rn(vw));
    *(uint2*)(dst + (size_t)q * 4) = pack4bf(vx, vy, vz, vw);
    *(uint2*)(dst + (size_t)k * CH + (size_t)q * 4) = pack4bf(vx - hx, vy - hy, vz - hz, vw - hw);
}

// fused level-2 gathers, vectorized: X (float4), R (uint4 = 8 bf16), C (scalar gather, 4-wide store)
__global__ void k_l2a_parv(const float4* __restrict__ src4, __nv_bfloat16* __restrict__ dstX,
                           const __nv_bfloat16* __restrict__ At,
                           __nv_bfloat16* __restrict__ R, __nv_bfloat16* __restrict__ Cb,
                           int kold, int kn) {
    int q = blockIdx.x * blockDim.x + threadIdx.x;
    int totx = kn * 64;                    // X units (4 ch)
    int totr = kn * kold / 8;              // R units (8 bf16)
    int totc = kold * kn / 4;              // C units (4 bf16)
    if (q < totx) {
        int r = q >> 6, c4 = q & 63;
        int p = g_perm[r];
        float sc = g_score[p];
        float4 v = src4[(size_t)p * 64 + c4];
        float vx = v.x * sc, vy = v.y * sc, vz = v.z * sc, vw = v.w * sc;
        float hx = __bfloat162float(__float2bfloat16_rn(vx));
        float hy = __bfloat162float(__float2bfloat16_rn(vy));
        float hz = __bfloat162float(__float2bfloat16_rn(vz));
        float hw = __bfloat162float(__float2bfloat16_rn(vw));
        *(uint2*)(dstX + (size_t)q * 4) = pack4bf(vx, vy, vz, vw);
        *(uint2*)(dstX + (size_t)kn * CH + (size_t)q * 4) = pack4bf(vx - hx, vy - hy, vz - hz, vw - hw);
        return;
    }
    int j = q - totx;
    if (j < totr) {
        int kold8 = kold / 8;
        int r = j / kold8, k8 = (j - r * kold8) * 8;
        int p = g_perm[r];
        uint4 v = *(const uint4*)(At + (size_t)p * kold + k8);
        if (p >= k8 && p < k8 + 8) {
            __nv_bfloat16* e = (__nv_bfloat16*)&v;
            e[p - k8] = __float2bfloat16_rn(1.0f);
        }
        *(uint4*)(R + (size_t)r * kold + k8) = v;
        return;
    }
    j -= totr;
    if (j < totc) {
        int kn4 = kn / 4;
        int k = j / kn4, c4 = (j - k * kn4) * 4;
        const __nv_bfloat16* Ak = At + (size_t)k * kold;
        __nv_bfloat16 o[4];
#pragma unroll
        for (int i = 0; i < 4; i++) {
            int p = g_perm[c4 + i];
            o[i] = (k == p) ? __float2bfloat16_rn(1.0f) : Ak[p];
        }
        *(uint2*)(Cb + (size_t)k * kn + c4) = *(uint2*)o;
    }
}

// ---------------- final readout ----------------
__global__ void k_rowsum_f(const float* __restrict__ F, int n) {
    int t = threadIdx.x;
    int rows = n / 32;
    float s = 0.f;
    int r0 = blockIdx.x * rows;
    for (int r = r0; r < r0 + rows; r++) s += F[(size_t)r * CH + t];
    g_fpart[blockIdx.x * 256 + t] = s;
}

__global__ void k_final(int n, const float* __restrict__ wc,
                        const float* __restrict__ bc, float* __restrict__ out, int out_size) {
    __shared__ float red[256];
    __shared__ float lg[16];
    int t = threadIdx.x;
    float s = 0.f;
#pragma unroll
    for (int b = 0; b < 32; b++) s += g_fpart[b * 256 + t];
    float mv = s / (float)n;
    red[t] = mv * mv; __syncthreads();
    for (int off = 128; off > 0; off >>= 1) { if (t < off) red[t] += red[t + off]; __syncthreads(); }
    float nrm = fmaxf(sqrtf(red[0]), 1e-12f);
    __syncthreads();
    float e = mv / nrm;
    for (int j = 0; j < 10; j++) {
        red[t] = e * wc[j * CH + t]; __syncthreads();
        for (int off = 128; off > 0; off >>= 1) { if (t < off) red[t] += red[t + off]; __syncthreads(); }
        if (t == 0) lg[j] = red[0] + bc[j];
        __syncthreads();
    }
    if (t == 0) {
        float mx = lg[0];
        for (int j = 1; j < 10; j++) mx = fmaxf(mx, lg[j]);
        float se = 0.f;
        for (int j = 0; j < 10; j++) se += expf(lg[j] - mx);
        float lse = logf(se) + mx;
        for (int j = 0; j < 10; j++) lg[j] -= lse;
    }
    __syncthreads();
    if (t < out_size && t < CH) out[t] = e;
    if (t < 10 && CH + t < out_size) out[CH + t] = lg[t];
    for (int idx = 266 + t; idx < out_size; idx += 256) out[idx] = 0.0f;
}

// ---------------- launch ----------------
extern "C" void kernel_launch(void* const* d_in, const int* in_sizes, int n_in,
                              void* d_out, int out_size) {
    const float* x  = (const float*)d_in[0];
    const int*   ei = (const int*)d_in[1];
    const float* w0 = (const float*)d_in[2];
    const float* b0 = (const float*)d_in[3];
    const float* w1 = (const float*)d_in[4];
    const float* b1 = (const float*)d_in[5];
    const float* w2 = (const float*)d_in[6];
    const float* b2 = (const float*)d_in[7];
    const float* p1 = (const float*)d_in[8];
    const float* p2 = (const float*)d_in[9];
    const float* wc = (const float*)d_in[10];
    const float* bc = (const float*)d_in[11];
    float* out = (float*)d_out;
    int E = in_sizes[1] / 2;
    const int n0 = N0, k1 = 2048, k2 = 1024;
    const int NW = CH * CH;

    float *pPart, *pfA, *pfB;
    __nv_bfloat16 *pAtb, *pRb, *pCbb, *pXb, *pWb, *pXwb;
    cudaGetSymbolAddress((void**)&pPart, g_part);
    cudaGetSymbolAddress((void**)&pfA, g_fA);
    cudaGetSymbolAddress((void**)&pfB, g_fB);
    cudaGetSymbolAddress((void**)&pAtb, g_Atb);
    cudaGetSymbolAddress((void**)&pRb,  g_Rb);
    cudaGetSymbolAddress((void**)&pCbb, g_Cbb);
    cudaGetSymbolAddress((void**)&pXb,  g_Xb);
    cudaGetSymbolAddress((void**)&pWb,  g_Wb);
    cudaGetSymbolAddress((void**)&pXwb, g_xwb);

    constexpr int SM22 = hgemm_smem<2, 2>();
    constexpr int SM12 = hgemm_smem<1, 2>();
    constexpr int SM11 = hgemm_smem<1, 1>();
    cudaFuncSetAttribute(k_hgemm<2, 2, 3, PAIRS_X>,
                         cudaFuncAttributeMaxDynamicSharedMemorySize, SM22);
    cudaFuncSetAttribute(k_hgemm<1, 2, 2, PAIRS_AGG>,
                         cudaFuncAttributeMaxDynamicSharedMemorySize, SM12);
    cudaFuncSetAttribute(k_hgemm<1, 1, 1, PAIRS_AA>,
                         cudaFuncAttributeMaxDynamicSharedMemorySize, SM11);

    // ---- graph build + conversions ----
    k_zs<<<16 + (n0 * CH + 3 * NW + 255) / 256, 256>>>(x, w0, w1, w2, pXb, pWb);
    k_fill<<<(E + 255) / 256, 256>>>(ei, E);

    // ---- GCN level 0 ----
    k_hgemm<2, 2, 3, PAIRS_X><<<dim3(2, 32, 2), 256, SM22>>>(pXb, pWb, pPart, 256, 256, 128,
                                                              n0, 256, (long)n0 * CH, (long)NW);
    k_reduceFv<<<n0 / 4, 256>>>((const float4*)pPart, (float4*)pfB, 2, n0, MODE_DINV0, nullptr, nullptr);
    k_agg0v<<<n0 / 4, 256>>>((const float4*)pfB, b0, pfA, p1);   // F0 + score1

    // ---- pool 1 ----
    k_threshcollect<<<1, 1024>>>(n0, k1);
    k_gather_xbv<<<(k1 * 64 + 255) / 256, 256>>>((const float4*)pfA, pXb, k1);

    // ---- augment level 1 ----
    k_augmentT<<<k1, 256>>>(pAtb);

    // ---- GCN level 1 ----
    k_hgemm<2, 2, 3, PAIRS_X><<<dim3(2, 16, 4), 256, SM22>>>(pXb, pWb + 2 * NW, pPart, 256, 256, 64,
                                                              k1, 256, (long)k1 * CH, (long)NW);
    k_reduce_ds2v<<<(k1 * 64 + 255) / 256, 256>>>((const float4*)pPart, pXwb, 4, k1, 256);
    k_hgemm<1, 2, 2, PAIRS_AGG><<<dim3(2, 16, 4), 256, SM12>>>(pAtb, pXwb, pPart, k1, 256, 512,
                                                                k1, 256, 0, (long)k1 * CH);
    k_reduceFv<<<k1 / 4, 256>>>((const float4*)pPart, (float4*)pfA, 4, k1, MODE_RELU,
                                (const float4*)b1, (const float4*)p2);   // F1 + score2

    // ---- pool 2 + fused gathers ----
    k_threshcollect<<<1, 1024>>>(k1, k2);
    k_l2a_parv<<<(k2 * 64 + k2 * k1 / 8 + k1 * k2 / 4 + 255) / 256, 256>>>(
        (const float4*)pfA, pXb, pAtb, pRb, pCbb, k1, k2);

    // ---- augment level 2 (GEMM) ----
    k_hgemm<1, 1, 1, PAIRS_AA><<<dim3(8, 8, 2), 256, SM11>>>(pRb, pCbb, pPart, k1, k2, 1024,
                                                              k2, k2, 0, 0);
    k_reduce_A2tv<<<k2, 256>>>((const float4*)pPart, pAtb, k2);  // Atb=A2t + dinv

    // ---- GCN level 2 ----
    k_hgemm<2, 2, 3, PAIRS_X><<<dim3(2, 8, 8), 256, SM22>>>(pXb, pWb + 4 * NW, pPart, 256, 256, 32,
                                                             k2, 256, (long)k2 * CH, (long)NW);
    k_reduce_ds2v<<<(k2 * 64 + 255) / 256, 256>>>((const float4*)pPart, pXwb, 8, k2, 256);
    k_hgemm<1, 2, 2, PAIRS_AGG><<<dim3(2, 8, 8), 256, SM12>>>(pAtb, pXwb, pPart, k2, 256, 128,
                                                               k2, 256, 0, (long)k2 * CH);
    k_reduceFv<<<k2 / 4, 256>>>((const float4*)pPart, (float4*)pfA, 8, k2, MODE_RELU,
                                (const float4*)b2, nullptr);     // F2

    // ---- readout ----
    k_rowsum_f<<<32, 256>>>(pfA, k2);
    k_final<<<1, 256>>>(k2, wc, bc, out, out_size);
}

// round 15
// speedup vs baseline: 1.3856x; 1.0050x over previous
#include <cuda_runtime.h>
#include <cuda_bf16.h>
#include <math.h>

#define N0 4096
#define CH 256
#define DEG 96

#define MODE_DINV0 0
#define MODE_DINV  1
#define MODE_RELU  2

#define PAIRS_X   0x011000
#define PAIRS_AGG 0x0100
#define PAIRS_AA  0x0

// ---------------- scratch ----------------
static __device__ __align__(16) float g_part[2 * 4096 * 256];
static __device__ __align__(16) __nv_bfloat16 g_Atb[2048 * 2048];
static __device__ __align__(16) __nv_bfloat16 g_Rb[1024 * 2048];
static __device__ __align__(16) __nv_bfloat16 g_Cbb[2048 * 1024];
static __device__ __align__(16) __nv_bfloat16 g_Xb[2 * N0 * CH];
static __device__ __align__(16) __nv_bfloat16 g_Wb[3 * 2 * CH * CH];
static __device__ __align__(16) __nv_bfloat16 g_xwb[2 * 2048 * CH];
static __device__ __align__(16) float g_fA[N0 * CH];
static __device__ __align__(16) float g_fB[N0 * CH];
static __device__ __align__(16) float g_fpart[32 * 256];
static __device__ float g_dinv[N0];
static __device__ float g_score[N0];
static __device__ int   g_perm[N0];
static __device__ int   g_csccnt[N0];
static __device__ int   g_srcs[N0 * DEG];
static __device__ int   g_cntdiag[N0];

__device__ __forceinline__ unsigned fkey(float f) {
    unsigned u = __float_as_uint(f);
    return (u & 0x80000000u) ? ~u : (u | 0x80000000u);
}

__device__ __forceinline__ uint2 pack4bf(float a, float b, float c, float d) {
    __nv_bfloat162 lo = __floats2bfloat162_rn(a, b);
    __nv_bfloat162 hi = __floats2bfloat162_rn(c, d);
    return make_uint2(*(unsigned*)&lo, *(unsigned*)&hi);
}

// degree for level-0 gcn_norm: all in-edges + (2 if no self loops)
__device__ __forceinline__ float deg0(int row) {
    int cd = g_cntdiag[row];
    return (float)(g_csccnt[row] + cd) + ((cd == 0) ? 2.0f : 0.0f);
}

// ---------------- zero + split-2 of x, w0, w1, w2 ----------------
__global__ void k_zs(const float* __restrict__ x, const float* __restrict__ w0,
                     const float* __restrict__ w1, const float* __restrict__ w2,
                     __nv_bfloat16* __restrict__ Xb, __nv_bfloat16* __restrict__ Wb) {
    const int nx = N0 * CH;
    const int nw = CH * CH;
    int id = blockIdx.x;
    if (id < 16) {
        int i = id * 256 + threadIdx.x;
        g_csccnt[i] = 0; g_cntdiag[i] = 0;
        return;
    }
    int idx = (id - 16) * 256 + threadIdx.x;
    float v; __nv_bfloat16 *hi, *lo;
    if (idx < nx) {
        v = x[idx];
        hi = Xb + idx; lo = Xb + nx + idx;
    } else {
        int j = idx - nx;
        if (j >= 3 * nw) return;
        int l = j >> 16, o = j & (nw - 1);
        v = (l == 0) ? w0[o] : (l == 1) ? w1[o] : w2[o];
        __nv_bfloat16* base = Wb + (size_t)l * 2 * nw;
        hi = base + o; lo = base + nw + o;
    }
    __nv_bfloat16 h = __float2bfloat16_rn(v);
    *hi = h;
    *lo = __float2bfloat16_rn(v - __bfloat162float(h));
}

__global__ void k_fill(const int* __restrict__ ei, int E) {
    int e = blockIdx.x * blockDim.x + threadIdx.x;
    if (e >= E) return;
    int s = ei[e], d = ei[e + E];
    if (s == d) {
        atomicAdd(&g_cntdiag[s], 1);
    } else {
        int pos = atomicAdd(&g_csccnt[d], 1);
        if (pos < DEG) g_srcs[d * DEG + pos] = s;
    }
}

// ---------------- bf16 HMMA GEMM (R8-proven) ----------------
__device__ __forceinline__ void mma16816(float* d, const unsigned* a, unsigned b0, unsigned b1) {
    asm volatile(
        "mma.sync.aligned.m16n8k16.row.col.f32.bf16.bf16.f32 "
        "{%0,%1,%2,%3}, {%4,%5,%6,%7}, {%8,%9}, {%0,%1,%2,%3};\n"
        : "+f"(d[0]), "+f"(d[1]), "+f"(d[2]), "+f"(d[3])
        : "r"(a[0]), "r"(a[1]), "r"(a[2]), "r"(a[3]), "r"(b0), "r"(b1));
}

template <int NA, int NB>
__host__ __device__ constexpr int hgemm_smem() {
    return 2 * (NA * 128 * 40 * 2 + NB * 16 * 136 * 4);
}

template <int NA, int NB, int NPAIR, int PAIRS>
__global__ void __launch_bounds__(256, 1)
k_hgemm(const __nv_bfloat16* __restrict__ A, const __nv_bfloat16* __restrict__ B,
        float* __restrict__ Cpart, int lda, int ldb, int chunk,
        int M, int N, long aStride, long bStride) {
    extern __shared__ char sm_raw[];
    __nv_bfloat16* Asm = (__nv_bfloat16*)sm_raw;
    unsigned* Bsm = (unsigned*)(sm_raw + 2 * NA * 128 * 40 * 2);

    int tid = threadIdx.x;
    int i0 = blockIdx.y * 128, j0 = blockIdx.x * 128;
    int kbeg = blockIdx.z * chunk, kend = kbeg + chunk;
    int w = tid >> 5, l = tid & 31;
    int wm = w & 3, wn = w >> 2;
    int mb = wm * 32, nb = wn * 64;
    int g = l >> 2, tg = l & 3;

    float acc[2][8][4];
#pragma unroll
    for (int mt = 0; mt < 2; mt++)
#pragma unroll
        for (int j = 0; j < 8; j++)
#pragma unroll
            for (int q = 0; q < 4; q++) acc[mt][j][q] = 0.f;

    int arow = tid >> 1, apart = tid & 1;
    int bkk = tid >> 4, bnseg = tid & 15;

    auto stage = [&](int st, int k0) {
#pragma unroll
        for (int q = 0; q < NA; q++) {
            const uint4* src = (const uint4*)&A[q * aStride + (size_t)(i0 + arow) * lda + k0 + apart * 16];
            uint4* dst = (uint4*)(Asm + ((size_t)(st * NA + q) * 128 + arow) * 40 + apart * 16);
            dst[0] = src[0]; dst[1] = src[1];
        }
#pragma unroll
        for (int p = 0; p < NB; p++) {
            const __nv_bfloat16* Bp = B + p * bStride;
            uint4 lo4 = *(const uint4*)&Bp[(size_t)(k0 + 2 * bkk) * ldb + j0 + bnseg * 8];
            uint4 hi4 = *(const uint4*)&Bp[(size_t)(k0 + 2 * bkk + 1) * ldb + j0 + bnseg * 8];
            unsigned* d = Bsm + ((size_t)(st * NB + p) * 16 + bkk) * 136 + bnseg * 8;
            *(uint4*)d = make_uint4(
                __byte_perm(lo4.x, hi4.x, 0x5410), __byte_perm(lo4.x, hi4.x, 0x7632),
                __byte_perm(lo4.y, hi4.y, 0x5410), __byte_perm(lo4.y, hi4.y, 0x7632));
            *(uint4*)(d + 4) = make_uint4(
                __byte_perm(lo4.z, hi4.z, 0x5410), __byte_perm(lo4.z, hi4.z, 0x7632),
                __byte_perm(lo4.w, hi4.w, 0x5410), __byte_perm(lo4.w, hi4.w, 0x7632));
        }
    };

    stage(0, kbeg);
    __syncthreads();

    for (int k0 = kbeg; k0 < kend; k0 += 32) {
        int cur = ((k0 - kbeg) >> 5) & 1;
        if (k0 + 32 < kend) stage(cur ^ 1, k0 + 32);
#pragma unroll
        for (int ks = 0; ks < 32; ks += 16) {
            unsigned a[NA][2][4];
#pragma unroll
            for (int q = 0; q < NA; q++) {
                const __nv_bfloat16* Aq = Asm + (size_t)(cur * NA + q) * 128 * 40;
#pragma unroll
                for (int mt = 0; mt < 2; mt++) {
                    int r0 = mb + mt * 16 + g;
                    a[q][mt][0] = *(const unsigned*)(Aq + r0 * 40 + ks + tg * 2);
                    a[q][mt][1] = *(const unsigned*)(Aq + (r0 + 8) * 40 + ks + tg * 2);
                    a[q][mt][2] = *(const unsigned*)(Aq + r0 * 40 + ks + tg * 2 + 8);
                    a[q][mt][3] = *(const unsigned*)(Aq + (r0 + 8) * 40 + ks + tg * 2 + 8);
                }
            }
            int kk0 = (ks >> 1) + tg;
#pragma unroll
            for (int p = 0; p < NPAIR; p++) {
                const int ai = (PAIRS >> (8 * p + 4)) & 0xF;
                const int bi = (PAIRS >> (8 * p)) & 0xF;
                const unsigned* Bq = Bsm + (size_t)(cur * NB + bi) * 16 * 136;
#pragma unroll
                for (int j = 0; j < 8; j++) {
                    int n = nb + j * 8 + g;
                    unsigned b0 = Bq[kk0 * 136 + n];
                    unsigned b1 = Bq[(kk0 + 4) * 136 + n];
                    mma16816(acc[0][j], a[ai][0], b0, b1);
                    mma16816(acc[1][j], a[ai][1], b0, b1);
                }
            }
        }
        __syncthreads();
    }
    float* Cp = Cpart + (size_t)blockIdx.z * M * N;
#pragma unroll
    for (int mt = 0; mt < 2; mt++) {
        int gr = i0 + mb + mt * 16 + g;
#pragma unroll
        for (int j = 0; j < 8; j++) {
            int gc = j0 + nb + j * 8 + tg * 2;
            *(float2*)&Cp[(size_t)gr * N + gc] = make_float2(acc[mt][j][0], acc[mt][j][1]);
            *(float2*)&Cp[(size_t)(gr + 8) * N + gc] = make_float2(acc[mt][j][2], acc[mt][j][3]);
        }
    }
}

// ---------------- vectorized split-K reduce: 4 rows/block, float4 ----------------
__global__ void k_reduceFv(const float4* __restrict__ Cpart4, float4* __restrict__ out4,
                           int SK, int M, int mode, const float4* __restrict__ bias4,
                           const float4* __restrict__ p4arr) {
    __shared__ float red[256], red2[256];
    int t = threadIdx.x;
    int grp = t >> 6, lane = t & 63;
    int row = blockIdx.x * 4 + grp;
    size_t idx = (size_t)row * 64 + lane;
    float4 s = Cpart4[idx];
    for (int z = 1; z < SK; z++) {
        float4 c = Cpart4[(size_t)z * M * 64 + idx];
        s.x += c.x; s.y += c.y; s.z += c.z; s.w += c.w;
    }
    float4 v;
    if (mode == MODE_DINV0) {
        float di = rsqrtf(deg0(row));
        v = make_float4(s.x * di, s.y * di, s.z * di, s.w * di);
    } else if (mode == MODE_DINV) {
        float di = g_dinv[row];
        v = make_float4(s.x * di, s.y * di, s.z * di, s.w * di);
    } else {
        float di = g_dinv[row];
        float4 b = bias4[lane];
        v.x = fmaxf(di * s.x + b.x, 0.f);
        v.y = fmaxf(di * s.y + b.y, 0.f);
        v.z = fmaxf(di * s.z + b.z, 0.f);
        v.w = fmaxf(di * s.w + b.w, 0.f);
    }
    out4[idx] = v;
    if (p4arr != nullptr) {
        float4 p = p4arr[lane];
        red[t]  = v.x * p.x + v.y * p.y + v.z * p.z + v.w * p.w;
        red2[t] = p.x * p.x + p.y * p.y + p.z * p.z + p.w * p.w;
        __syncthreads();
#pragma unroll
        for (int off = 32; off > 0; off >>= 1) {
            if (lane < off) { red[t] += red[t + off]; red2[t] += red2[t + off]; }
            __syncthreads();
        }
        if (lane == 0) g_score[row] = tanhf(red[t] * rsqrtf(red2[t]));
    }
}

// vectorized split-K reduce -> dinv -> split-2 bf16 planes (N fixed at 256)
__global__ void k_reduce_ds2v(const float4* __restrict__ Cpart4, __nv_bfloat16* __restrict__ out,
                              int SK, int M) {
    int q = blockIdx.x * blockDim.x + threadIdx.x;
    int tot4 = M * 64;
    if (q >= tot4) return;
    float4 s = Cpart4[q];
    for (int z = 1; z < SK; z++) {
        float4 c = Cpart4[(size_t)z * tot4 + q];
        s.x += c.x; s.y += c.y; s.z += c.z; s.w += c.w;
    }
    float di = g_dinv[q >> 6];
    float vx = s.x * di, vy = s.y * di, vz = s.z * di, vw = s.w * di;
    float hx = __bfloat162float(__float2bfloat16_rn(vx));
    float hy = __bfloat162float(__float2bfloat16_rn(vy));
    float hz = __bfloat162float(__float2bfloat16_rn(vz));
    float hw = __bfloat162float(__float2bfloat16_rn(vw));
    *(uint2*)(out + (size_t)q * 4) = pack4bf(vx, vy, vz, vw);
    *(uint2*)(out + (size_t)M * 256 + (size_t)q * 4) = pack4bf(vx - hx, vy - hy, vz - hz, vw - hw);
}

// vectorized A2^T reduce: one block/row, float4 loads, 4-bf16 stores, rowsum->dinv
__global__ void k_reduce_A2tv(const float4* __restrict__ Cpart4, __nv_bfloat16* __restrict__ out,
                              int n) {
    __shared__ float red[256];
    int row = blockIdx.x, t = threadIdx.x;
    int n4 = n / 4;
    int tot4 = n * n / 4;
    float part = 0.f;
    for (int c4 = t; c4 < n4; c4 += 256) {
        size_t idx = (size_t)row * n4 + c4;
        float4 a = Cpart4[idx];
        float4 b = Cpart4[(size_t)tot4 + idx];
        float vx = a.x + b.x, vy = a.y + b.y, vz = a.z + b.z, vw = a.w + b.w;
        int c = c4 * 4;
        if (row >= c && row < c + 4) {
            if (row == c)     vx = 2.0f;
            if (row == c + 1) vy = 2.0f;
            if (row == c + 2) vz = 2.0f;
            if (row == c + 3) vw = 2.0f;
        }
        *(uint2*)(out + (size_t)row * n + c) = pack4bf(vx, vy, vz, vw);
        part += vx + vy + vz + vw;
    }
    red[t] = part; __syncthreads();
    for (int off = 128; off > 0; off >>= 1) { if (t < off) red[t] += red[t + off]; __syncthreads(); }
    if (t == 0) g_dinv[row] = rsqrtf(red[0]);
}

// ---------------- level-0 aggregation: float4, 4 rows/block, fused score ----------------
__global__ void k_agg0v(const float4* __restrict__ B4, const float* __restrict__ bias,
                        float* __restrict__ out, const float* __restrict__ p) {
    __shared__ float red[256], red2[256];
    int t = threadIdx.x;
    int grp = t >> 6, lane = t & 63;
    int d = blockIdx.x * 4 + grp;
    int cd = g_cntdiag[d];
    float w0 = (cd == 0) ? 2.0f : (float)cd;
    float4 b = B4[(size_t)d * 64 + lane];
    float4 a0 = make_float4(w0 * b.x, w0 * b.y, w0 * b.z, w0 * b.w);
    float4 a1 = make_float4(0.f, 0.f, 0.f, 0.f);
    int rawcnt = g_csccnt[d];
    int cnt = min(rawcnt, DEG);
    const int* src = &g_srcs[d * DEG];
    int e = 0;
    for (; e + 2 <= cnt; e += 2) {
        int s0 = __ldg(&src[e]), s1 = __ldg(&src[e + 1]);
        float4 v0 = B4[(size_t)s0 * 64 + lane];
        float4 v1 = B4[(size_t)s1 * 64 + lane];
        a0.x += v0.x; a0.y += v0.y; a0.z += v0.z; a0.w += v0.w;
        a1.x += v1.x; a1.y += v1.y; a1.z += v1.z; a1.w += v1.w;
    }
    if (e < cnt) {
        int s0 = __ldg(&src[e]);
        float4 v0 = B4[(size_t)s0 * 64 + lane];
        a0.x += v0.x; a0.y += v0.y; a0.z += v0.z; a0.w += v0.w;
    }
    float deg = (float)(rawcnt + cd) + ((cd == 0) ? 2.0f : 0.0f);
    float di = rsqrtf(deg);
    float4 b4 = ((const float4*)bias)[lane];
    float4 v;
    v.x = fmaxf(di * (a0.x + a1.x) + b4.x, 0.f);
    v.y = fmaxf(di * (a0.y + a1.y) + b4.y, 0.f);
    v.z = fmaxf(di * (a0.z + a1.z) + b4.z, 0.f);
    v.w = fmaxf(di * (a0.w + a1.w) + b4.w, 0.f);
    ((float4*)out)[(size_t)d * 64 + lane] = v;
    float4 p4 = ((const float4*)p)[lane];
    red[t]  = v.x * p4.x + v.y * p4.y + v.z * p4.z + v.w * p4.w;
    red2[t] = p4.x * p4.x + p4.y * p4.y + p4.z * p4.z + p4.w * p4.w;
    __syncthreads();
#pragma unroll
    for (int off = 32; off > 0; off >>= 1) {
        if (lane < off) { red[t] += red[t + off]; red2[t] += red2[t + off]; }
        __syncthreads();
    }
    if (lane == 0) g_score[d] = tanhf(red[t] * rsqrtf(red2[t]));
}

// ---------------- level-1 augment ----------------
__global__ void k_augmentT(__nv_bfloat16* __restrict__ Atb) {
    __shared__ float s[N0];
    __shared__ int sp[2048];
    __shared__ float red[256];
    int r = blockIdx.x, t = threadIdx.x;
    for (int c = t; c < N0; c += 256) s[c] = 0.f;
    for (int c = t; c < 2048; c += 256) sp[c] = g_perm[c];
    __syncthreads();
    int i = sp[r];
    int lane = t & 31, w = t >> 5;
    int cnt = min(g_csccnt[i], DEG);
    const int* isrc = &g_srcs[i * DEG];
    for (int e = w; e < cnt; e += 8) {
        int kc = isrc[e];
        if (lane == 0) atomicAdd(&s[kc], 2.0f);
        int cnt2 = min(g_csccnt[kc], DEG);
        const int* ksrc = &g_srcs[kc * DEG];
        for (int f = lane; f < cnt2; f += 32) atomicAdd(&s[ksrc[f]], 1.0f);
    }
    __syncthreads();
    __nv_bfloat16* row = Atb + (size_t)r * 2048;
    float part = 0.f;
    for (int c = t; c < 2048; c += 256) {
        float v = (c == r) ? 2.0f : s[sp[c]];
        row[c] = __float2bfloat16_rn(v);
        part += v;
    }
    red[t] = part; __syncthreads();
    for (int off = 128; off > 0; off >>= 1) { if (t < off) red[t] += red[t + off]; __syncthreads(); }
    if (t == 0) g_dinv[r] = rsqrtf(red[0]);
}

// ---------------- top-k threshold + collect: 1 barrier per bit ----------------
__global__ void k_threshcollect(int n, int k) {
    __shared__ unsigned u[N0];
    __shared__ int cnt[34];     // [0..31] per-bit counts, [32] cg, [33..] collect counters
    __shared__ int sc[2];
    int t = threadIdx.x;
    int lane = t & 31;
    int per = n >> 10;
    for (int i = t; i < n; i += 1024) u[i] = fkey(g_score[i]);
    if (t < 34) cnt[t] = 0;
    if (t < 2) sc[t] = 0;
    __syncthreads();
    unsigned thr = 0;
    for (int bit = 31; bit >= 0; --bit) {
        unsigned cand = thr | (1u << bit);
        int c = 0;
        for (int j = 0; j < per; j++)
            c += (u[j * 1024 + t] >= cand) ? 1 : 0;
#pragma unroll
        for (int off = 16; off; off >>= 1) c += __shfl_down_sync(0xffffffffu, c, off);
        if (lane == 0 && c) atomicAdd(&cnt[bit], c);
        __syncthreads();
        if (cnt[bit] >= k) thr = cand;
    }
    {
        int c = 0;
        for (int j = 0; j < per; j++)
            c += (u[j * 1024 + t] > thr) ? 1 : 0;
#pragma unroll
        for (int off = 16; off; off >>= 1) c += __shfl_down_sync(0xffffffffu, c, off);
        if (lane == 0 && c) atomicAdd(&cnt[32], c);
        __syncthreads();
    }
    int cg = cnt[32];
    for (int i = t; i < n; i += 1024) {
        unsigned v = u[i];
        if (v > thr) {
            int p = atomicAdd(&sc[0], 1);
            g_perm[p] = i;
        } else if (v == thr) {
            int p = atomicAdd(&sc[1], 1);
            int pos = cg + p;
            if (pos < k) g_perm[pos] = i;
        }
    }
}

// vectorized gather + gate + split-2 (level 1)
__global__ void k_gather_xbv(const float4* __restrict__ src4, __nv_bfloat16* __restrict__ dst, int k) {
    int q = blockIdx.x * blockDim.x + threadIdx.x;
    int tot4 = k * 64;
    if (q >= tot4) return;
    int r = q >> 6, c4 = q & 63;
    int p = g_perm[r];
    float sc = g_score[p];
    float4 v = src4[(size_t)p * 64 + c4];
    float vx = v.x * sc, vy = v.y * sc, vz = v.z * sc, vw = v.w * sc;
    float hx = __bfloat162float(__float2bfloat16_rn(vx));
    float hy = __bfloat162float(__float2bfloat16_rn(vy));
    float hz = __bfloat162float(__float2bfloat16_rn(vz));
    float hw = __bfloat162float(__float2bfloat16_rn(vw));
    *(uint2*)(dst + (size_t)q * 4) = pack4bf(vx, vy, vz, vw);
    *(uint2*)(dst + (size_t)k * CH + (size_t)q * 4) = pack4bf(vx - hx, vy - hy, vz - hz, vw - hw);
}

// fused level-2 gathers, vectorized
__global__ void k_l2a_parv(const float4* __restrict__ src4, __nv_bfloat16* __restrict__ dstX,
                           const __nv_bfloat16* __restrict__ At,
                           __nv_bfloat16* __restrict__ R, __nv_bfloat16* __restrict__ Cb,
                           int kold, int kn) {
    int q = blockIdx.x * blockDim.x + threadIdx.x;
    int totx = kn * 64;
    int totr = kn * kold / 8;
    int totc = kold * kn / 4;
    if (q < totx) {
        int r = q >> 6, c4 = q & 63;
        int p = g_perm[r];
        float sc = g_score[p];
        float4 v = src4[(size_t)p * 64 + c4];
        float vx = v.x * sc, vy = v.y * sc, vz = v.z * sc, vw = v.w * sc;
        float hx = __bfloat162float(__float2bfloat16_rn(vx));
        float hy = __bfloat162float(__float2bfloat16_rn(vy));
        float hz = __bfloat162float(__float2bfloat16_rn(vz));
        float hw = __bfloat162float(__float2bfloat16_rn(vw));
        *(uint2*)(dstX + (size_t)q * 4) = pack4bf(vx, vy, vz, vw);
        *(uint2*)(dstX + (size_t)kn * CH + (size_t)q * 4) = pack4bf(vx - hx, vy - hy, vz - hz, vw - hw);
        return;
    }
    int j = q - totx;
    if (j < totr) {
        int kold8 = kold / 8;
        int r = j / kold8, k8 = (j - r * kold8) * 8;
        int p = g_perm[r];
        uint4 v = *(const uint4*)(At + (size_t)p * kold + k8);
        if (p >= k8 && p < k8 + 8) {
            __nv_bfloat16* e = (__nv_bfloat16*)&v;
            e[p - k8] = __float2bfloat16_rn(1.0f);
        }
        *(uint4*)(R + (size_t)r * kold + k8) = v;
        return;
    }
    j -= totr;
    if (j < totc) {
        int kn4 = kn / 4;
        int k = j / kn4, c4 = (j - k * kn4) * 4;
        const __nv_bfloat16* Ak = At + (size_t)k * kold;
        __nv_bfloat16 o[4];
#pragma unroll
        for (int i = 0; i < 4; i++) {
            int p = g_perm[c4 + i];
            o[i] = (k == p) ? __float2bfloat16_rn(1.0f) : Ak[p];
        }
        *(uint2*)(Cb + (size_t)k * kn + c4) = *(uint2*)o;
    }
}

// ---------------- final readout ----------------
__global__ void k_rowsum_f(const float* __restrict__ F, int n) {
    int t = threadIdx.x;
    int rows = n / 32;
    float s = 0.f;
    int r0 = blockIdx.x * rows;
    for (int r = r0; r < r0 + rows; r++) s += F[(size_t)r * CH + t];
    g_fpart[blockIdx.x * 256 + t] = s;
}

__global__ void k_final(int n, const float* __restrict__ wc,
                        const float* __restrict__ bc, float* __restrict__ out, int out_size) {
    __shared__ float red[256];
    __shared__ float lg[16];
    int t = threadIdx.x;
    float s = 0.f;
#pragma unroll
    for (int b = 0; b < 32; b++) s += g_fpart[b * 256 + t];
    float mv = s / (float)n;
    red[t] = mv * mv; __syncthreads();
    for (int off = 128; off > 0; off >>= 1) { if (t < off) red[t] += red[t + off]; __syncthreads(); }
    float nrm = fmaxf(sqrtf(red[0]), 1e-12f);
    __syncthreads();
    float e = mv / nrm;
    for (int j = 0; j < 10; j++) {
        red[t] = e * wc[j * CH + t]; __syncthreads();
        for (int off = 128; off > 0; off >>= 1) { if (t < off) red[t] += red[t + off]; __syncthreads(); }
        if (t == 0) lg[j] = red[0] + bc[j];
        __syncthreads();
    }
    if (t == 0) {
        float mx = lg[0];
        for (int j = 1; j < 10; j++) mx = fmaxf(mx, lg[j]);
        float se = 0.f;
        for (int j = 0; j < 10; j++) se += expf(lg[j] - mx);
        float lse = logf(se) + mx;
        for (int j = 0; j < 10; j++) lg[j] -= lse;
    }
    __syncthreads();
    if (t < out_size && t < CH) out[t] = e;
    if (t < 10 && CH + t < out_size) out[CH + t] = lg[t];
    for (int idx = 266 + t; idx < out_size; idx += 256) out[idx] = 0.0f;
}

// ---------------- launch ----------------
extern "C" void kernel_launch(void* const* d_in, const int* in_sizes, int n_in,
                              void* d_out, int out_size) {
    const float* x  = (const float*)d_in[0];
    const int*   ei = (const int*)d_in[1];
    const float* w0 = (const float*)d_in[2];
    const float* b0 = (const float*)d_in[3];
    const float* w1 = (const float*)d_in[4];
    const float* b1 = (const float*)d_in[5];
    const float* w2 = (const float*)d_in[6];
    const float* b2 = (const float*)d_in[7];
    const float* p1 = (const float*)d_in[8];
    const float* p2 = (const float*)d_in[9];
    const float* wc = (const float*)d_in[10];
    const float* bc = (const float*)d_in[11];
    float* out = (float*)d_out;
    int E = in_sizes[1] / 2;
    const int n0 = N0, k1 = 2048, k2 = 1024;
    const int NW = CH * CH;

    float *pPart, *pfA, *pfB;
    __nv_bfloat16 *pAtb, *pRb, *pCbb, *pXb, *pWb, *pXwb;
    cudaGetSymbolAddress((void**)&pPart, g_part);
    cudaGetSymbolAddress((void**)&pfA, g_fA);
    cudaGetSymbolAddress((void**)&pfB, g_fB);
    cudaGetSymbolAddress((void**)&pAtb, g_Atb);
    cudaGetSymbolAddress((void**)&pRb,  g_Rb);
    cudaGetSymbolAddress((void**)&pCbb, g_Cbb);
    cudaGetSymbolAddress((void**)&pXb,  g_Xb);
    cudaGetSymbolAddress((void**)&pWb,  g_Wb);
    cudaGetSymbolAddress((void**)&pXwb, g_xwb);

    constexpr int SM22 = hgemm_smem<2, 2>();
    constexpr int SM12 = hgemm_smem<1, 2>();
    constexpr int SM11 = hgemm_smem<1, 1>();
    cudaFuncSetAttribute(k_hgemm<2, 2, 3, PAIRS_X>,
                         cudaFuncAttributeMaxDynamicSharedMemorySize, SM22);
    cudaFuncSetAttribute(k_hgemm<1, 2, 2, PAIRS_AGG>,
                         cudaFuncAttributeMaxDynamicSharedMemorySize, SM12);
    cudaFuncSetAttribute(k_hgemm<1, 1, 1, PAIRS_AA>,
                         cudaFuncAttributeMaxDynamicSharedMemorySize, SM11);

    // ---- graph build + conversions ----
    k_zs<<<16 + (n0 * CH + 3 * NW + 255) / 256, 256>>>(x, w0, w1, w2, pXb, pWb);
    k_fill<<<(E + 255) / 256, 256>>>(ei, E);

    // ---- GCN level 0 ----
    k_hgemm<2, 2, 3, PAIRS_X><<<dim3(2, 32, 2), 256, SM22>>>(pXb, pWb, pPart, 256, 256, 128,
                                                              n0, 256, (long)n0 * CH, (long)NW);
    k_reduceFv<<<n0 / 4, 256>>>((const float4*)pPart, (float4*)pfB, 2, n0, MODE_DINV0, nullptr, nullptr);
    k_agg0v<<<n0 / 4, 256>>>((const float4*)pfB, b0, pfA, p1);   // F0 + score1

    // ---- pool 1 ----
    k_threshcollect<<<1, 1024>>>(n0, k1);
    k_gather_xbv<<<(k1 * 64 + 255) / 256, 256>>>((const float4*)pfA, pXb, k1);

    // ---- augment level 1 ----
    k_augmentT<<<k1, 256>>>(pAtb);

    // ---- GCN level 1 ----
    k_hgemm<2, 2, 3, PAIRS_X><<<dim3(2, 16, 4), 256, SM22>>>(pXb, pWb + 2 * NW, pPart, 256, 256, 64,
                                                              k1, 256, (long)k1 * CH, (long)NW);
    k_reduce_ds2v<<<(k1 * 64 + 255) / 256, 256>>>((const float4*)pPart, pXwb, 4, k1);
    k_hgemm<1, 2, 2, PAIRS_AGG><<<dim3(2, 16, 4), 256, SM12>>>(pAtb, pXwb, pPart, k1, 256, 512,
                                                                k1, 256, 0, (long)k1 * CH);
    k_reduceFv<<<k1 / 4, 256>>>((const float4*)pPart, (float4*)pfA, 4, k1, MODE_RELU,
                                (const float4*)b1, (const float4*)p2);   // F1 + score2

    // ---- pool 2 + fused gathers ----
    k_threshcollect<<<1, 1024>>>(k1, k2);
    k_l2a_parv<<<(k2 * 64 + k2 * k1 / 8 + k1 * k2 / 4 + 255) / 256, 256>>>(
        (const float4*)pfA, pXb, pAtb, pRb, pCbb, k1, k2);

    // ---- augment level 2 (GEMM) ----
    k_hgemm<1, 1, 1, PAIRS_AA><<<dim3(8, 8, 2), 256, SM11>>>(pRb, pCbb, pPart, k1, k2, 1024,
                                                              k2, k2, 0, 0);
    k_reduce_A2tv<<<k2, 256>>>((const float4*)pPart, pAtb, k2);  // Atb=A2t + dinv

    // ---- GCN level 2 ----
    k_hgemm<2, 2, 3, PAIRS_X><<<dim3(2, 8, 8), 256, SM22>>>(pXb, pWb + 4 * NW, pPart, 256, 256, 32,
                                                             k2, 256, (long)k2 * CH, (long)NW);
    k_reduce_ds2v<<<(k2 * 64 + 255) / 256, 256>>>((const float4*)pPart, pXwb, 8, k2);
    k_hgemm<1, 2, 2, PAIRS_AGG><<<dim3(2, 8, 8), 256, SM12>>>(pAtb, pXwb, pPart, k2, 256, 128,
                                                               k2, 256, 0, (long)k2 * CH);
    k_reduceFv<<<k2 / 4, 256>>>((const float4*)pPart, (float4*)pfA, 8, k2, MODE_RELU,
                                (const float4*)b2, nullptr);     // F2

    // ---- readout ----
    k_rowsum_f<<<32, 256>>>(pfA, k2);
    k_final<<<1, 256>>>(k2, wc, bc, out, out_size);
}